// round 1
// baseline (speedup 1.0000x reference)
#include <cuda_runtime.h>
#include <math.h>
#include <stdint.h>

// Problem constants
#define NB   128      // drugs (batch)
#define NS1  16       // substructure tokens
#define NDQ  300      // drug feature dim
#define NC   256      // classes
#define NS2  8        // semantic tokens
#define ND   256      // semantic dim
#define MQ   (NB*NS1) // 2048
#define MK   (NC*NS2) // 2048

struct Scratch {
    float Q[MQ * ND];           // 2048x256
    float K[MK * ND];           // 2048x256
    float V[MK * ND];           // 2048x256
    float S[(size_t)MQ * MK];   // 2048x2048 scores
    float proto[(size_t)NB * NC * ND]; // 128x256x256
    float npe[(size_t)NB * NC * ND];   // 128x256x256
    float center[NB * ND];
    float nd[NB * ND];
    float ce[NB];
    float rm1[NB * NC];
    float rm2[NB];
};
__device__ Scratch g_scratch;

// ---------------------------------------------------------------------------
// Generic 64x64 tiled SGEMM, 256 threads, 4x4 microtile. C = alpha * A @ B(^T)
// M, N multiples of 64; K arbitrary (guarded).
// ---------------------------------------------------------------------------
template <bool TRANSB>
__global__ void sgemm64(const float* __restrict__ A, const float* __restrict__ B,
                        float* __restrict__ C, int M, int N, int K, float alpha) {
    __shared__ float As[64][17];
    __shared__ float Bs[64][17];
    int tid = threadIdx.x;
    int tx = tid & 15, ty = tid >> 4;
    int m0 = blockIdx.y * 64, n0 = blockIdx.x * 64;

    float acc[4][4];
#pragma unroll
    for (int i = 0; i < 4; i++)
#pragma unroll
        for (int j = 0; j < 4; j++) acc[i][j] = 0.f;

    for (int k0 = 0; k0 < K; k0 += 16) {
#pragma unroll
        for (int i = 0; i < 4; i++) {
            int idx = tid + 256 * i;
            int r = idx >> 4, kk = idx & 15;
            int kg = k0 + kk;
            As[r][kk] = (kg < K) ? A[(size_t)(m0 + r) * K + kg] : 0.f;
        }
        if (TRANSB) {
#pragma unroll
            for (int i = 0; i < 4; i++) {
                int idx = tid + 256 * i;
                int r = idx >> 4, kk = idx & 15;
                int kg = k0 + kk;
                Bs[r][kk] = (kg < K) ? B[(size_t)(n0 + r) * K + kg] : 0.f;
            }
        } else {
#pragma unroll
            for (int i = 0; i < 4; i++) {
                int idx = tid + 256 * i;
                int kk = idx >> 6, n = idx & 63;
                int kg = k0 + kk;
                Bs[n][kk] = (kg < K) ? B[(size_t)kg * N + n0 + n] : 0.f;
            }
        }
        __syncthreads();
#pragma unroll
        for (int kk = 0; kk < 16; kk++) {
            float a[4], bb[4];
#pragma unroll
            for (int i = 0; i < 4; i++) a[i] = As[ty * 4 + i][kk];
#pragma unroll
            for (int j = 0; j < 4; j++) bb[j] = Bs[tx * 4 + j][kk];
#pragma unroll
            for (int i = 0; i < 4; i++)
#pragma unroll
                for (int j = 0; j < 4; j++) acc[i][j] += a[i] * bb[j];
        }
        __syncthreads();
    }
#pragma unroll
    for (int i = 0; i < 4; i++)
#pragma unroll
        for (int j = 0; j < 4; j++)
            C[(size_t)(m0 + ty * 4 + i) * N + n0 + tx * 4 + j] = alpha * acc[i][j];
}

// ---------------------------------------------------------------------------
// softmax over S2, mean over S1, proto = abar @ V
// grid (C, 8), 256 threads; each block handles one class c and 16 b's.
// ---------------------------------------------------------------------------
__global__ void softmax_proto(const float* __restrict__ S, const float* __restrict__ V,
                              float* __restrict__ proto) {
    int c = blockIdx.x;
    int by = blockIdx.y;
    int t = threadIdx.x;
    __shared__ float Vs[8][256];
    __shared__ float ab[16][8];
    __shared__ float abar[8];

    for (int i = t; i < 8 * 256; i += 256)
        Vs[i >> 8][i & 255] = V[(size_t)c * 8 * 256 + i];
    __syncthreads();

    for (int bi = 0; bi < 16; bi++) {
        int b = by * 16 + bi;
        if (t < 16) {
            const float* row = S + (size_t)(b * 16 + t) * 2048 + c * 8;
            float v[8];
            float mx = -1e30f;
#pragma unroll
            for (int j = 0; j < 8; j++) { v[j] = row[j]; mx = fmaxf(mx, v[j]); }
            float s = 0.f;
#pragma unroll
            for (int j = 0; j < 8; j++) { v[j] = expf(v[j] - mx); s += v[j]; }
            float inv = 1.f / (16.f * s);
#pragma unroll
            for (int j = 0; j < 8; j++) ab[t][j] = v[j] * inv;
        }
        __syncthreads();
        if (t < 8) {
            float s = 0.f;
#pragma unroll
            for (int s1 = 0; s1 < 16; s1++) s += ab[s1][t];
            abar[t] = s;
        }
        __syncthreads();
        float acc = 0.f;
#pragma unroll
        for (int j = 0; j < 8; j++) acc += abar[j] * Vs[j][t];
        proto[((size_t)b * 256 + c) * 256 + t] = acc;
    }
}

// ---------------------------------------------------------------------------
// Per-b: center, n_d (normalized), logits, CE part.  grid 128, 256 threads.
// ---------------------------------------------------------------------------
__global__ void logits_center_ce(const float* __restrict__ proto, const float* __restrict__ left,
                                 const int* __restrict__ ids, float* __restrict__ center,
                                 float* __restrict__ nd, float* __restrict__ ce_part) {
    int b = blockIdx.x;
    int t = threadIdx.x;
    __shared__ float red[256];
    __shared__ float lf[256];
    __shared__ float lgs[256];
    const float* pb = proto + (size_t)b * 65536;

    // center[b][t] = mean_c proto[b][c][t]
    float s = 0.f;
    for (int c = 0; c < 256; c++) s += pb[(size_t)c * 256 + t];
    float ctr = s * (1.f / 256.f);
    center[b * 256 + t] = ctr;

    float lv = left[b * 256 + t];
    lf[t] = lv;

    // n_d = normalize(left - center)
    float v = lv - ctr;
    red[t] = v * v;
    __syncthreads();
    for (int off = 128; off > 0; off >>= 1) {
        if (t < off) red[t] += red[t + off];
        __syncthreads();
    }
    float nrm = sqrtf(red[0]);
    nd[b * 256 + t] = v / fmaxf(nrm, 1e-12f);
    __syncthreads();

    // logits[t] = dot(left[b], proto[b][t]) / TEMPERATURE
    float dot = 0.f;
    for (int d = 0; d < 256; d++) dot += lf[d] * pb[(size_t)t * 256 + d];
    float lg = dot * (1.0f / 0.9f);
    lgs[t] = lg;

    // log-sum-exp
    red[t] = lg;
    __syncthreads();
    for (int off = 128; off > 0; off >>= 1) {
        if (t < off) red[t] = fmaxf(red[t], red[t + off]);
        __syncthreads();
    }
    float mx = red[0];
    __syncthreads();
    red[t] = expf(lg - mx);
    __syncthreads();
    for (int off = 128; off > 0; off >>= 1) {
        if (t < off) red[t] += red[t + off];
        __syncthreads();
    }
    if (t == 0) {
        float lse = mx + logf(red[0]);
        ce_part[b] = lse - lgs[ids[b]];
    }
}

// ---------------------------------------------------------------------------
// npe = normalize(proto - center).  grid 32768 (b*256+c), 256 threads.
// ---------------------------------------------------------------------------
__global__ void npe_kernel(const float* __restrict__ proto, const float* __restrict__ center,
                           float* __restrict__ npe) {
    int i = blockIdx.x;
    int b = i >> 8;
    int t = threadIdx.x;
    __shared__ float red[256];
    float v = proto[(size_t)i * 256 + t] - center[b * 256 + t];
    red[t] = v * v;
    __syncthreads();
    for (int off = 128; off > 0; off >>= 1) {
        if (t < off) red[t] += red[t + off];
        __syncthreads();
    }
    float nrm = sqrtf(red[0]);
    npe[(size_t)i * 256 + t] = v / fmaxf(nrm, 1e-12f);
}

// ---------------------------------------------------------------------------
// Per-b Gram G = npe_b @ npe_b^T (256x256, K=256), fused rowmax(G - I).
// grid (4 row-chunks, 128 b), 256 threads, 4x4 microtile.
// ---------------------------------------------------------------------------
__global__ void gram_rowmax(const float* __restrict__ npe, float* __restrict__ rowmax) {
    int b = blockIdx.y;
    int r0 = blockIdx.x * 64;
    const float* Nb = npe + (size_t)b * 65536;
    __shared__ float As[64][17];
    __shared__ float Bs[64][17];
    int tid = threadIdx.x;
    int tx = tid & 15, ty = tid >> 4;

    float rmax[4] = {-1e30f, -1e30f, -1e30f, -1e30f};

    for (int ct = 0; ct < 4; ct++) {
        int c0 = ct * 64;
        float acc[4][4];
#pragma unroll
        for (int i = 0; i < 4; i++)
#pragma unroll
            for (int j = 0; j < 4; j++) acc[i][j] = 0.f;

        for (int k0 = 0; k0 < 256; k0 += 16) {
#pragma unroll
            for (int i = 0; i < 4; i++) {
                int idx = tid + 256 * i;
                int r = idx >> 4, kk = idx & 15;
                As[r][kk] = Nb[(size_t)(r0 + r) * 256 + k0 + kk];
            }
#pragma unroll
            for (int i = 0; i < 4; i++) {
                int idx = tid + 256 * i;
                int r = idx >> 4, kk = idx & 15;
                Bs[r][kk] = Nb[(size_t)(c0 + r) * 256 + k0 + kk];
            }
            __syncthreads();
#pragma unroll
            for (int kk = 0; kk < 16; kk++) {
                float a[4], bb[4];
#pragma unroll
                for (int i = 0; i < 4; i++) a[i] = As[ty * 4 + i][kk];
#pragma unroll
                for (int j = 0; j < 4; j++) bb[j] = Bs[tx * 4 + j][kk];
#pragma unroll
                for (int i = 0; i < 4; i++)
#pragma unroll
                    for (int j = 0; j < 4; j++) acc[i][j] += a[i] * bb[j];
            }
            __syncthreads();
        }
#pragma unroll
        for (int i = 0; i < 4; i++) {
            int r = r0 + ty * 4 + i;
#pragma unroll
            for (int j = 0; j < 4; j++) {
                int cgl = c0 + tx * 4 + j;
                float v = acc[i][j] - (r == cgl ? 1.f : 0.f);
                rmax[i] = fmaxf(rmax[i], v);
            }
        }
    }
    // reduce across tx (16 lanes of each half-warp)
#pragma unroll
    for (int off = 8; off > 0; off >>= 1)
#pragma unroll
        for (int i = 0; i < 4; i++)
            rmax[i] = fmaxf(rmax[i], __shfl_xor_sync(0xffffffffu, rmax[i], off));
    if (tx == 0)
#pragma unroll
        for (int i = 0; i < 4; i++)
            rowmax[b * 256 + r0 + ty * 4 + i] = rmax[i];
}

// ---------------------------------------------------------------------------
// loss2: dcos rowmax.  grid 128 (row i), 256 threads (first 128 compute dots).
// ---------------------------------------------------------------------------
__global__ void dcos_rowmax(const float* __restrict__ nd, float* __restrict__ rowmax2) {
    int i = blockIdx.x;
    int t = threadIdx.x;
    __shared__ float xi[256];
    __shared__ float red[256];
    xi[t] = nd[i * 256 + t];
    __syncthreads();
    float m = -1e30f;
    if (t < 128) {
        float s = 0.f;
        const float* xj = nd + t * 256;
        for (int d = 0; d < 256; d++) s += xi[d] * xj[d];
        m = s - (i == t ? 1.f : 0.f);
    }
    red[t] = m;
    __syncthreads();
    for (int off = 128; off > 0; off >>= 1) {
        if (t < off) red[t] = fmaxf(red[t], red[t + off]);
        __syncthreads();
    }
    if (t == 0) rowmax2[i] = red[0];
}

// ---------------------------------------------------------------------------
// Final deterministic reduction -> scalar loss.
// ---------------------------------------------------------------------------
__global__ void finalize(const float* __restrict__ ce_part, const float* __restrict__ rm1,
                         const float* __restrict__ rm2, float* __restrict__ out, int out_size) {
    int t = threadIdx.x;
    __shared__ float ra[256], rb[256], rc[256];
    float a = 0.f, b2 = 0.f, c2 = 0.f;
    for (int i = t; i < 128; i += 256) { a += ce_part[i]; c2 += rm2[i]; }
    for (int i = t; i < 32768; i += 256) b2 += rm1[i];
    ra[t] = a; rb[t] = b2; rc[t] = c2;
    __syncthreads();
    for (int off = 128; off > 0; off >>= 1) {
        if (t < off) {
            ra[t] += ra[t + off];
            rb[t] += rb[t + off];
            rc[t] += rc[t + off];
        }
        __syncthreads();
    }
    if (t == 0) {
        float loss = ra[0] / 128.f + 0.7f * (rb[0] / 32768.f + rc[0] / 128.f);
        for (int i = 0; i < out_size; i++) out[i] = loss;
    }
}

// ---------------------------------------------------------------------------
extern "C" void kernel_launch(void* const* d_in, const int* in_sizes, int n_in,
                              void* d_out, int out_size) {
    const float* left = (const float*)d_in[0];
    const float* drug = (const float*)d_in[1];
    const float* sem  = (const float*)d_in[2];
    const float* Wq   = (const float*)d_in[3];
    const float* Wk   = (const float*)d_in[4];
    const float* Wv   = (const float*)d_in[5];
    const int*   ids  = (const int*)d_in[6];
    float* out = (float*)d_out;

    void* p = nullptr;
    cudaGetSymbolAddress(&p, g_scratch);
    Scratch* s = (Scratch*)p;

    const float inv_sqrt_dk = 0.05773502691896258f;  // 1/sqrt(300)

    // Projections
    sgemm64<false><<<dim3(ND / 64, MQ / 64), 256>>>(drug, Wq, s->Q, MQ, ND, NDQ, 1.f);
    sgemm64<false><<<dim3(ND / 64, MK / 64), 256>>>(sem, Wk, s->K, MK, ND, ND, 1.f);
    sgemm64<false><<<dim3(ND / 64, MK / 64), 256>>>(sem, Wv, s->V, MK, ND, ND, 1.f);
    // Scores S = (Q @ K^T) / sqrt(300)
    sgemm64<true><<<dim3(MK / 64, MQ / 64), 256>>>(s->Q, s->K, s->S, MQ, MK, ND, inv_sqrt_dk);
    // softmax over S2, mean over S1, proto
    softmax_proto<<<dim3(NC, 8), 256>>>(s->S, s->V, s->proto);
    // center, n_d, logits, CE
    logits_center_ce<<<NB, 256>>>(s->proto, left, ids, s->center, s->nd, s->ce);
    // npe
    npe_kernel<<<NB * NC, 256>>>(s->proto, s->center, s->npe);
    // loss1 rowmax
    gram_rowmax<<<dim3(4, NB), 256>>>(s->npe, s->rm1);
    // loss2 rowmax
    dcos_rowmax<<<NB, 256>>>(s->nd, s->rm2);
    // combine
    finalize<<<1, 256>>>(s->ce, s->rm1, s->rm2, out, out_size);
}

// round 2
// speedup vs baseline: 1.6035x; 1.6035x over previous
#include <cuda_runtime.h>
#include <math.h>
#include <stdint.h>

#define NB   128
#define NS1  16
#define NDQ  300
#define NC   256
#define NS2  8
#define ND   256
#define MQ   (NB*NS1) // 2048
#define MK   (NC*NS2) // 2048

struct alignas(128) Scratch {
    float Q[MQ * ND];
    float K[MK * ND];
    float V[MK * ND];
    float S[(size_t)MQ * MK];           // 2048x2048
    float proto[(size_t)NB * NC * ND];  // 128x256x256
    float center[NB * ND];
    float nd[NB * ND];
    float invn[NB * NC];
    float ce[NB];
    float rm1p[NB * 2 * NC];            // per-b, per-col-tile partial rowmax
    float rm2[NB];
};
__device__ Scratch g_scratch;

// ---------------------------------------------------------------------------
// Old 64x64 SGEMM (kept for the 3 projections; K=300 guard needed)
// ---------------------------------------------------------------------------
__global__ void sgemm64_nn(const float* __restrict__ A, const float* __restrict__ B,
                           float* __restrict__ C, int M, int N, int K) {
    __shared__ float As[64][17];
    __shared__ float Bs[64][17];
    int tid = threadIdx.x;
    int tx = tid & 15, ty = tid >> 4;
    int m0 = blockIdx.y * 64, n0 = blockIdx.x * 64;
    float acc[4][4];
#pragma unroll
    for (int i = 0; i < 4; i++)
#pragma unroll
        for (int j = 0; j < 4; j++) acc[i][j] = 0.f;
    for (int k0 = 0; k0 < K; k0 += 16) {
#pragma unroll
        for (int i = 0; i < 4; i++) {
            int idx = tid + 256 * i;
            int r = idx >> 4, kk = idx & 15;
            int kg = k0 + kk;
            As[r][kk] = (kg < K) ? A[(size_t)(m0 + r) * K + kg] : 0.f;
        }
#pragma unroll
        for (int i = 0; i < 4; i++) {
            int idx = tid + 256 * i;
            int kk = idx >> 6, n = idx & 63;
            int kg = k0 + kk;
            Bs[n][kk] = (kg < K) ? B[(size_t)kg * N + n0 + n] : 0.f;
        }
        __syncthreads();
#pragma unroll
        for (int kk = 0; kk < 16; kk++) {
            float a[4], bb[4];
#pragma unroll
            for (int i = 0; i < 4; i++) a[i] = As[ty * 4 + i][kk];
#pragma unroll
            for (int j = 0; j < 4; j++) bb[j] = Bs[tx * 4 + j][kk];
#pragma unroll
            for (int i = 0; i < 4; i++)
#pragma unroll
                for (int j = 0; j < 4; j++) acc[i][j] += a[i] * bb[j];
        }
        __syncthreads();
    }
#pragma unroll
    for (int i = 0; i < 4; i++)
#pragma unroll
        for (int j = 0; j < 4; j++)
            C[(size_t)(m0 + ty * 4 + i) * N + n0 + tx * 4 + j] = acc[i][j];
}

// ---------------------------------------------------------------------------
// 128x128x8 SGEMM, C = alpha * A @ B^T. A: [M,K] rm, B: [N,K] rm.
// 256 threads, 8x8 microtile, float4 smem loads, global prefetch.
// Requires: M%128==0, N%128==0, K%8==0, K%8 alignment for float4 (K%4==0).
// ---------------------------------------------------------------------------
#define BM 128
#define BN 128
#define BK 8

__global__ void sgemm_tt(const float* __restrict__ A, const float* __restrict__ B,
                         float* __restrict__ C, int M, int N, int K, float alpha) {
    __shared__ float As[BK][BM + 4];
    __shared__ float Bs[BK][BN + 4];
    int tid = threadIdx.x;
    int tx = tid & 15, ty = tid >> 4;
    int m0 = blockIdx.y * BM, n0 = blockIdx.x * BN;
    int lr = tid >> 1;
    int lk = (tid & 1) * 4;
    const float* Aptr = A + (size_t)(m0 + lr) * K + lk;
    const float* Bptr = B + (size_t)(n0 + lr) * K + lk;

    float acc[8][8];
#pragma unroll
    for (int i = 0; i < 8; i++)
#pragma unroll
        for (int j = 0; j < 8; j++) acc[i][j] = 0.f;

    float4 a4 = *(const float4*)(Aptr);
    float4 b4 = *(const float4*)(Bptr);

    for (int k0 = 0; k0 < K; k0 += BK) {
        As[lk + 0][lr] = a4.x; As[lk + 1][lr] = a4.y;
        As[lk + 2][lr] = a4.z; As[lk + 3][lr] = a4.w;
        Bs[lk + 0][lr] = b4.x; Bs[lk + 1][lr] = b4.y;
        Bs[lk + 2][lr] = b4.z; Bs[lk + 3][lr] = b4.w;
        __syncthreads();
        if (k0 + BK < K) {
            a4 = *(const float4*)(Aptr + k0 + BK);
            b4 = *(const float4*)(Bptr + k0 + BK);
        }
#pragma unroll
        for (int kk = 0; kk < BK; kk++) {
            float a[8], b[8];
            *(float4*)(a)     = *(const float4*)&As[kk][ty * 8];
            *(float4*)(a + 4) = *(const float4*)&As[kk][ty * 8 + 4];
            *(float4*)(b)     = *(const float4*)&Bs[kk][tx * 8];
            *(float4*)(b + 4) = *(const float4*)&Bs[kk][tx * 8 + 4];
#pragma unroll
            for (int i = 0; i < 8; i++)
#pragma unroll
                for (int j = 0; j < 8; j++) acc[i][j] += a[i] * b[j];
        }
        __syncthreads();
    }
#pragma unroll
    for (int i = 0; i < 8; i++) {
        float* crow = C + (size_t)(m0 + ty * 8 + i) * N + n0 + tx * 8;
#pragma unroll
        for (int j = 0; j < 8; j += 4) {
            float4 v = make_float4(alpha * acc[i][j], alpha * acc[i][j + 1],
                                   alpha * acc[i][j + 2], alpha * acc[i][j + 3]);
            *(float4*)(crow + j) = v;
        }
    }
}

// ---------------------------------------------------------------------------
// Fused per-b Gram: X = proto[b] - center[b] (256x256), G = X X^T scaled by
// inv norms, minus identity, partial rowmax per 128-col tile.
// grid (cb=2, rb=2, b=128), 256 threads.
// ---------------------------------------------------------------------------
__global__ void gram_rowmax(const float* __restrict__ proto, const float* __restrict__ center,
                            const float* __restrict__ invn, float* __restrict__ rm1p) {
    __shared__ float As[BK][BM + 4];
    __shared__ float Bs[BK][BN + 4];
    int b = blockIdx.z;
    int r0 = blockIdx.y * BM, c0 = blockIdx.x * BN;
    const float* X = proto + (size_t)b * NC * ND;
    const float* ctr = center + b * ND;
    int tid = threadIdx.x;
    int tx = tid & 15, ty = tid >> 4;
    int lr = tid >> 1;
    int lk = (tid & 1) * 4;
    const float* Aptr = X + (size_t)(r0 + lr) * ND + lk;
    const float* Bptr = X + (size_t)(c0 + lr) * ND + lk;

    float acc[8][8];
#pragma unroll
    for (int i = 0; i < 8; i++)
#pragma unroll
        for (int j = 0; j < 8; j++) acc[i][j] = 0.f;

    float4 a4 = *(const float4*)(Aptr);
    float4 b4 = *(const float4*)(Bptr);
    float4 c4 = *(const float4*)(ctr + lk);

    for (int k0 = 0; k0 < ND; k0 += BK) {
        As[lk + 0][lr] = a4.x - c4.x; As[lk + 1][lr] = a4.y - c4.y;
        As[lk + 2][lr] = a4.z - c4.z; As[lk + 3][lr] = a4.w - c4.w;
        Bs[lk + 0][lr] = b4.x - c4.x; Bs[lk + 1][lr] = b4.y - c4.y;
        Bs[lk + 2][lr] = b4.z - c4.z; Bs[lk + 3][lr] = b4.w - c4.w;
        __syncthreads();
        if (k0 + BK < ND) {
            a4 = *(const float4*)(Aptr + k0 + BK);
            b4 = *(const float4*)(Bptr + k0 + BK);
            c4 = *(const float4*)(ctr + k0 + BK + lk);
        }
#pragma unroll
        for (int kk = 0; kk < BK; kk++) {
            float a[8], bb[8];
            *(float4*)(a)      = *(const float4*)&As[kk][ty * 8];
            *(float4*)(a + 4)  = *(const float4*)&As[kk][ty * 8 + 4];
            *(float4*)(bb)     = *(const float4*)&Bs[kk][tx * 8];
            *(float4*)(bb + 4) = *(const float4*)&Bs[kk][tx * 8 + 4];
#pragma unroll
            for (int i = 0; i < 8; i++)
#pragma unroll
                for (int j = 0; j < 8; j++) acc[i][j] += a[i] * bb[j];
        }
        __syncthreads();
    }

    float ir[8], ic[8];
#pragma unroll
    for (int i = 0; i < 8; i++) ir[i] = invn[b * NC + r0 + ty * 8 + i];
#pragma unroll
    for (int j = 0; j < 8; j++) ic[j] = invn[b * NC + c0 + tx * 8 + j];

    float rmax[8];
#pragma unroll
    for (int i = 0; i < 8; i++) {
        int r = r0 + ty * 8 + i;
        float m = -1e30f;
#pragma unroll
        for (int j = 0; j < 8; j++) {
            int cg = c0 + tx * 8 + j;
            float v = acc[i][j] * ir[i] * ic[j] - (r == cg ? 1.f : 0.f);
            m = fmaxf(m, v);
        }
        rmax[i] = m;
    }
    // reduce across the 16 tx lanes (same ty within one warp half)
#pragma unroll
    for (int off = 8; off > 0; off >>= 1)
#pragma unroll
        for (int i = 0; i < 8; i++)
            rmax[i] = fmaxf(rmax[i], __shfl_xor_sync(0xffffffffu, rmax[i], off));
    if (tx == 0) {
#pragma unroll
        for (int i = 0; i < 8; i++)
            rm1p[((size_t)b * 2 + blockIdx.x) * NC + r0 + ty * 8 + i] = rmax[i];
    }
}

// ---------------------------------------------------------------------------
// softmax over S2, mean over S1, proto = abar @ V. grid (C, 8), 256 thr.
// ---------------------------------------------------------------------------
__global__ void softmax_proto(const float* __restrict__ S, const float* __restrict__ V,
                              float* __restrict__ proto) {
    int c = blockIdx.x;
    int by = blockIdx.y;
    int t = threadIdx.x;
    __shared__ float Vs[8][256];
    __shared__ float ab[16][8];
    __shared__ float abar[8];

    for (int i = t; i < 8 * 256; i += 256)
        Vs[i >> 8][i & 255] = V[(size_t)c * 8 * 256 + i];
    __syncthreads();

    for (int bi = 0; bi < 16; bi++) {
        int b = by * 16 + bi;
        if (t < 16) {
            const float* row = S + (size_t)(b * 16 + t) * 2048 + c * 8;
            float v[8];
            float mx = -1e30f;
#pragma unroll
            for (int j = 0; j < 8; j++) { v[j] = row[j]; mx = fmaxf(mx, v[j]); }
            float s = 0.f;
#pragma unroll
            for (int j = 0; j < 8; j++) { v[j] = expf(v[j] - mx); s += v[j]; }
            float inv = 1.f / (16.f * s);
#pragma unroll
            for (int j = 0; j < 8; j++) ab[t][j] = v[j] * inv;
        }
        __syncthreads();
        if (t < 8) {
            float s = 0.f;
#pragma unroll
            for (int s1 = 0; s1 < 16; s1++) s += ab[s1][t];
            abar[t] = s;
        }
        __syncthreads();
        float acc = 0.f;
#pragma unroll
        for (int j = 0; j < 8; j++) acc += abar[j] * Vs[j][t];
        proto[((size_t)b * 256 + c) * 256 + t] = acc;
        __syncthreads();
    }
}

// ---------------------------------------------------------------------------
// Per-b: center, n_d, logits (warp-cooperative, coalesced), CE. grid 128.
// ---------------------------------------------------------------------------
__global__ void logits_center_ce(const float* __restrict__ proto, const float* __restrict__ left,
                                 const int* __restrict__ ids, float* __restrict__ center,
                                 float* __restrict__ nd, float* __restrict__ ce_part) {
    int b = blockIdx.x;
    int t = threadIdx.x;
    __shared__ float red[256];
    __shared__ float lf[256];
    __shared__ float lgs[256];
    const float* pb = proto + (size_t)b * 65536;

    float s = 0.f;
    for (int c = 0; c < 256; c++) s += pb[(size_t)c * 256 + t];
    float ctr = s * (1.f / 256.f);
    center[b * 256 + t] = ctr;

    float lv = left[b * 256 + t];
    lf[t] = lv;

    float v = lv - ctr;
    red[t] = v * v;
    __syncthreads();
    for (int off = 128; off > 0; off >>= 1) {
        if (t < off) red[t] += red[t + off];
        __syncthreads();
    }
    float nrm = sqrtf(red[0]);
    nd[b * 256 + t] = v / fmaxf(nrm, 1e-12f);
    __syncthreads();

    // logits: warp w handles c in [w*32, w*32+32)
    int w = t >> 5, lane = t & 31;
    float4 l0 = *(const float4*)&lf[lane * 8];
    float4 l1 = *(const float4*)&lf[lane * 8 + 4];
    for (int cc = 0; cc < 32; cc++) {
        int c = w * 32 + cc;
        const float* pr = pb + (size_t)c * 256 + lane * 8;
        float4 x0 = *(const float4*)pr;
        float4 x1 = *(const float4*)(pr + 4);
        float d = x0.x * l0.x + x0.y * l0.y + x0.z * l0.z + x0.w * l0.w
                + x1.x * l1.x + x1.y * l1.y + x1.z * l1.z + x1.w * l1.w;
#pragma unroll
        for (int off = 16; off > 0; off >>= 1) d += __shfl_xor_sync(0xffffffffu, d, off);
        if (lane == 0) lgs[c] = d * (1.0f / 0.9f);
    }
    __syncthreads();

    float lg = lgs[t];
    red[t] = lg;
    __syncthreads();
    for (int off = 128; off > 0; off >>= 1) {
        if (t < off) red[t] = fmaxf(red[t], red[t + off]);
        __syncthreads();
    }
    float mx = red[0];
    __syncthreads();
    red[t] = expf(lg - mx);
    __syncthreads();
    for (int off = 128; off > 0; off >>= 1) {
        if (t < off) red[t] += red[t + off];
        __syncthreads();
    }
    if (t == 0) {
        float lse = mx + logf(red[0]);
        ce_part[b] = lse - lgs[ids[b]];
    }
}

// ---------------------------------------------------------------------------
// invn[b*256+c] = 1 / max(||proto[b][c] - center[b]||, eps). 8 warps/block,
// each warp one (b,c) row. grid 4096.
// ---------------------------------------------------------------------------
__global__ void center_invnorm(const float* __restrict__ proto, const float* __restrict__ center,
                               float* __restrict__ invn) {
    int t = threadIdx.x;
    int w = t >> 5, lane = t & 31;
    int i = blockIdx.x * 8 + w;      // (b,c) index
    int b = i >> 8;
    const float* pr = proto + (size_t)i * 256 + lane * 8;
    const float* cr = center + b * 256 + lane * 8;
    float4 x0 = *(const float4*)pr;
    float4 x1 = *(const float4*)(pr + 4);
    float4 c0 = *(const float4*)cr;
    float4 c1 = *(const float4*)(cr + 4);
    float dx;
    float s = 0.f;
    dx = x0.x - c0.x; s += dx * dx;
    dx = x0.y - c0.y; s += dx * dx;
    dx = x0.z - c0.z; s += dx * dx;
    dx = x0.w - c0.w; s += dx * dx;
    dx = x1.x - c1.x; s += dx * dx;
    dx = x1.y - c1.y; s += dx * dx;
    dx = x1.z - c1.z; s += dx * dx;
    dx = x1.w - c1.w; s += dx * dx;
#pragma unroll
    for (int off = 16; off > 0; off >>= 1) s += __shfl_xor_sync(0xffffffffu, s, off);
    if (lane == 0) invn[i] = 1.f / fmaxf(sqrtf(s), 1e-12f);
}

// ---------------------------------------------------------------------------
// loss2: dcos rowmax.
// ---------------------------------------------------------------------------
__global__ void dcos_rowmax(const float* __restrict__ nd, float* __restrict__ rowmax2) {
    int i = blockIdx.x;
    int t = threadIdx.x;
    __shared__ float xi[256];
    __shared__ float red[256];
    xi[t] = nd[i * 256 + t];
    __syncthreads();
    float m = -1e30f;
    if (t < 128) {
        float s = 0.f;
        const float* xj = nd + t * 256;
        for (int d = 0; d < 256; d++) s += xi[d] * xj[d];
        m = s - (i == t ? 1.f : 0.f);
    }
    red[t] = m;
    __syncthreads();
    for (int off = 128; off > 0; off >>= 1) {
        if (t < off) red[t] = fmaxf(red[t], red[t + off]);
        __syncthreads();
    }
    if (t == 0) rowmax2[i] = red[0];
}

// ---------------------------------------------------------------------------
// Final deterministic reduction.
// ---------------------------------------------------------------------------
__global__ void finalize(const float* __restrict__ ce_part, const float* __restrict__ rm1p,
                         const float* __restrict__ rm2, float* __restrict__ out, int out_size) {
    int t = threadIdx.x;
    __shared__ float ra[256], rb[256], rc[256];
    float a = 0.f, b2 = 0.f, c2 = 0.f;
    for (int i = t; i < 128; i += 256) { a += ce_part[i]; c2 += rm2[i]; }
    for (int i = t; i < 32768; i += 256) {
        int b = i >> 8, r = i & 255;
        float v = fmaxf(rm1p[((size_t)b * 2 + 0) * 256 + r], rm1p[((size_t)b * 2 + 1) * 256 + r]);
        b2 += v;
    }
    ra[t] = a; rb[t] = b2; rc[t] = c2;
    __syncthreads();
    for (int off = 128; off > 0; off >>= 1) {
        if (t < off) {
            ra[t] += ra[t + off];
            rb[t] += rb[t + off];
            rc[t] += rc[t + off];
        }
        __syncthreads();
    }
    if (t == 0) {
        float loss = ra[0] / 128.f + 0.7f * (rb[0] / 32768.f + rc[0] / 128.f);
        for (int i = 0; i < out_size; i++) out[i] = loss;
    }
}

// ---------------------------------------------------------------------------
extern "C" void kernel_launch(void* const* d_in, const int* in_sizes, int n_in,
                              void* d_out, int out_size) {
    const float* left = (const float*)d_in[0];
    const float* drug = (const float*)d_in[1];
    const float* sem  = (const float*)d_in[2];
    const float* Wq   = (const float*)d_in[3];
    const float* Wk   = (const float*)d_in[4];
    const float* Wv   = (const float*)d_in[5];
    const int*   ids  = (const int*)d_in[6];
    float* out = (float*)d_out;

    void* p = nullptr;
    cudaGetSymbolAddress(&p, g_scratch);
    Scratch* s = (Scratch*)p;

    const float inv_sqrt_dk = 0.05773502691896258f;  // 1/sqrt(300)

    // Projections (old kernel, K guard for 300)
    sgemm64_nn<<<dim3(ND / 64, MQ / 64), 256>>>(drug, Wq, s->Q, MQ, ND, NDQ);
    sgemm64_nn<<<dim3(ND / 64, MK / 64), 256>>>(sem, Wk, s->K, MK, ND, ND);
    sgemm64_nn<<<dim3(ND / 64, MK / 64), 256>>>(sem, Wv, s->V, MK, ND, ND);
    // Scores S = (Q @ K^T) / sqrt(300)   [128x128 tiled, fp32]
    sgemm_tt<<<dim3(MK / BN, MQ / BM), 256>>>(s->Q, s->K, s->S, MQ, MK, ND, inv_sqrt_dk);
    // softmax over S2, mean over S1, proto
    softmax_proto<<<dim3(NC, 8), 256>>>(s->S, s->V, s->proto);
    // center, n_d, logits, CE
    logits_center_ce<<<NB, 256>>>(s->proto, left, ids, s->center, s->nd, s->ce);
    // inverse norms of centered prototypes
    center_invnorm<<<NB * NC / 8, 256>>>(s->proto, s->center, s->invn);
    // fused centered-Gram + scale + rowmax partials
    gram_rowmax<<<dim3(2, 2, NB), 256>>>(s->proto, s->center, s->invn, s->rm1p);
    // loss2
    dcos_rowmax<<<NB, 256>>>(s->nd, s->rm2);
    // combine
    finalize<<<1, 256>>>(s->ce, s->rm1p, s->rm2, out, out_size);
}

// round 3
// speedup vs baseline: 1.9606x; 1.2227x over previous
#include <cuda_runtime.h>
#include <math.h>
#include <stdint.h>

#define NB   128
#define NS1  16
#define NDQ  300
#define NC   256
#define NS2  8
#define ND   256
#define MQ   (NB*NS1) // 2048
#define MK   (NC*NS2) // 2048

struct alignas(128) Scratch {
    float Q[MQ * ND];
    float K[MK * ND];
    float V[MK * ND];
    float S[(size_t)MQ * MK];           // 2048x2048
    float proto[(size_t)NB * NC * ND];  // 128x256x256
    float center[NB * ND];
    float nd[NB * ND];
    float invn[NB * NC];
    float ce[NB];
    float rm1p[NB * 2 * NC];            // per-b, per-col-tile partial rowmax
    float rm2[NB];
};
__device__ Scratch g_scratch;

// ---------------------------------------------------------------------------
// 64x64 SGEMM NN (projections; K guard for 300)
// ---------------------------------------------------------------------------
__global__ void sgemm64_nn(const float* __restrict__ A, const float* __restrict__ B,
                           float* __restrict__ C, int M, int N, int K) {
    __shared__ float As[64][17];
    __shared__ float Bs[64][17];
    int tid = threadIdx.x;
    int tx = tid & 15, ty = tid >> 4;
    int m0 = blockIdx.y * 64, n0 = blockIdx.x * 64;
    float acc[4][4];
#pragma unroll
    for (int i = 0; i < 4; i++)
#pragma unroll
        for (int j = 0; j < 4; j++) acc[i][j] = 0.f;
    for (int k0 = 0; k0 < K; k0 += 16) {
#pragma unroll
        for (int i = 0; i < 4; i++) {
            int idx = tid + 256 * i;
            int r = idx >> 4, kk = idx & 15;
            int kg = k0 + kk;
            As[r][kk] = (kg < K) ? A[(size_t)(m0 + r) * K + kg] : 0.f;
        }
#pragma unroll
        for (int i = 0; i < 4; i++) {
            int idx = tid + 256 * i;
            int kk = idx >> 6, n = idx & 63;
            int kg = k0 + kk;
            Bs[n][kk] = (kg < K) ? B[(size_t)kg * N + n0 + n] : 0.f;
        }
        __syncthreads();
#pragma unroll
        for (int kk = 0; kk < 16; kk++) {
            float a[4], bb[4];
#pragma unroll
            for (int i = 0; i < 4; i++) a[i] = As[ty * 4 + i][kk];
#pragma unroll
            for (int j = 0; j < 4; j++) bb[j] = Bs[tx * 4 + j][kk];
#pragma unroll
            for (int i = 0; i < 4; i++)
#pragma unroll
                for (int j = 0; j < 4; j++) acc[i][j] += a[i] * bb[j];
        }
        __syncthreads();
    }
#pragma unroll
    for (int i = 0; i < 4; i++)
#pragma unroll
        for (int j = 0; j < 4; j++)
            C[(size_t)(m0 + ty * 4 + i) * N + n0 + tx * 4 + j] = acc[i][j];
}

// ---------------------------------------------------------------------------
// 128x128x8 fp32 SGEMM, C = alpha * A @ B^T (scores).
// ---------------------------------------------------------------------------
#define BM 128
#define BN 128
#define BK 8

__global__ void sgemm_tt(const float* __restrict__ A, const float* __restrict__ B,
                         float* __restrict__ C, int M, int N, int K, float alpha) {
    __shared__ float As[BK][BM + 4];
    __shared__ float Bs[BK][BN + 4];
    int tid = threadIdx.x;
    int tx = tid & 15, ty = tid >> 4;
    int m0 = blockIdx.y * BM, n0 = blockIdx.x * BN;
    int lr = tid >> 1;
    int lk = (tid & 1) * 4;
    const float* Aptr = A + (size_t)(m0 + lr) * K + lk;
    const float* Bptr = B + (size_t)(n0 + lr) * K + lk;

    float acc[8][8];
#pragma unroll
    for (int i = 0; i < 8; i++)
#pragma unroll
        for (int j = 0; j < 8; j++) acc[i][j] = 0.f;

    float4 a4 = *(const float4*)(Aptr);
    float4 b4 = *(const float4*)(Bptr);

    for (int k0 = 0; k0 < K; k0 += BK) {
        As[lk + 0][lr] = a4.x; As[lk + 1][lr] = a4.y;
        As[lk + 2][lr] = a4.z; As[lk + 3][lr] = a4.w;
        Bs[lk + 0][lr] = b4.x; Bs[lk + 1][lr] = b4.y;
        Bs[lk + 2][lr] = b4.z; Bs[lk + 3][lr] = b4.w;
        __syncthreads();
        if (k0 + BK < K) {
            a4 = *(const float4*)(Aptr + k0 + BK);
            b4 = *(const float4*)(Bptr + k0 + BK);
        }
#pragma unroll
        for (int kk = 0; kk < BK; kk++) {
            float a[8], b[8];
            *(float4*)(a)     = *(const float4*)&As[kk][ty * 8];
            *(float4*)(a + 4) = *(const float4*)&As[kk][ty * 8 + 4];
            *(float4*)(b)     = *(const float4*)&Bs[kk][tx * 8];
            *(float4*)(b + 4) = *(const float4*)&Bs[kk][tx * 8 + 4];
#pragma unroll
            for (int i = 0; i < 8; i++)
#pragma unroll
                for (int j = 0; j < 8; j++) acc[i][j] += a[i] * b[j];
        }
        __syncthreads();
    }
#pragma unroll
    for (int i = 0; i < 8; i++) {
        float* crow = C + (size_t)(m0 + ty * 8 + i) * N + n0 + tx * 8;
#pragma unroll
        for (int j = 0; j < 8; j += 4) {
            float4 v = make_float4(alpha * acc[i][j], alpha * acc[i][j + 1],
                                   alpha * acc[i][j + 2], alpha * acc[i][j + 3]);
            *(float4*)(crow + j) = v;
        }
    }
}

// ---------------------------------------------------------------------------
// tf32 tensor-core fused Gram + rowmax.
// grid (cb=2, rb=2, b=128), 256 threads = 8 warps (4 row x 2 col).
// Each block: G-tile [128 rows x 128 cols] of (X X^T)*ir*ic - I, rowmax out.
// ---------------------------------------------------------------------------
__device__ __forceinline__ uint32_t f2tf32(float x) {
    uint32_t r;
    asm("cvt.rna.tf32.f32 %0, %1;" : "=r"(r) : "f"(x));
    return r;
}
__device__ __forceinline__ void mma_tf32(float* d, const uint32_t* a, uint32_t b0, uint32_t b1) {
    asm volatile(
        "mma.sync.aligned.m16n8k8.row.col.f32.tf32.tf32.f32 "
        "{%0,%1,%2,%3},{%4,%5,%6,%7},{%8,%9},{%0,%1,%2,%3};"
        : "+f"(d[0]), "+f"(d[1]), "+f"(d[2]), "+f"(d[3])
        : "r"(a[0]), "r"(a[1]), "r"(a[2]), "r"(a[3]), "r"(b0), "r"(b1));
}

#define GSTR 12  // padded slice row stride (floats)

__global__ void gram_rowmax_tf32(const float* __restrict__ proto, const float* __restrict__ center,
                                 const float* __restrict__ invn, float* __restrict__ rm1p) {
    __shared__ uint32_t As[128 * GSTR];
    __shared__ uint32_t Bs[128 * GSTR];
    __shared__ float rmax_s[2][128];

    int b = blockIdx.z;
    int r0 = blockIdx.y * 128, c0 = blockIdx.x * 128;
    const float* X = proto + (size_t)b * NC * ND;
    const float* ctr = center + b * ND;

    int t = threadIdx.x;
    int w = t >> 5, lane = t & 31;
    int w_row = w >> 1, w_col = w & 1;
    int qrow = lane >> 2, qcol = lane & 3;

    // loader indices: thread t loads row lrow, 4-float chunk lpart of the k-slice
    int lrow = t >> 1;
    int lpart = (t & 1) * 4;

    const float* Ag = X + (size_t)(r0 + lrow) * ND + lpart;
    const float* Bg = X + (size_t)(c0 + lrow) * ND + lpart;

    float acc[2][8][4];
#pragma unroll
    for (int mi = 0; mi < 2; mi++)
#pragma unroll
        for (int nt = 0; nt < 8; nt++)
#pragma unroll
            for (int j = 0; j < 4; j++) acc[mi][nt][j] = 0.f;

    float4 pa = *(const float4*)(Ag);
    float4 pb = *(const float4*)(Bg);
    float4 pc = *(const float4*)(ctr + lpart);

    for (int k0 = 0; k0 < ND; k0 += 8) {
        uint32_t* ad = &As[lrow * GSTR + lpart];
        ad[0] = f2tf32(pa.x - pc.x); ad[1] = f2tf32(pa.y - pc.y);
        ad[2] = f2tf32(pa.z - pc.z); ad[3] = f2tf32(pa.w - pc.w);
        uint32_t* bd = &Bs[lrow * GSTR + lpart];
        bd[0] = f2tf32(pb.x - pc.x); bd[1] = f2tf32(pb.y - pc.y);
        bd[2] = f2tf32(pb.z - pc.z); bd[3] = f2tf32(pb.w - pc.w);
        __syncthreads();
        if (k0 + 8 < ND) {
            pa = *(const float4*)(Ag + k0 + 8);
            pb = *(const float4*)(Bg + k0 + 8);
            pc = *(const float4*)(ctr + k0 + 8 + lpart);
        }
        uint32_t afr[2][4];
#pragma unroll
        for (int mi = 0; mi < 2; mi++) {
            int mr = w_row * 32 + mi * 16 + qrow;
            afr[mi][0] = As[mr * GSTR + qcol];
            afr[mi][1] = As[(mr + 8) * GSTR + qcol];
            afr[mi][2] = As[mr * GSTR + qcol + 4];
            afr[mi][3] = As[(mr + 8) * GSTR + qcol + 4];
        }
#pragma unroll
        for (int nt = 0; nt < 8; nt++) {
            int nr = w_col * 64 + nt * 8 + qrow;
            uint32_t b0 = Bs[nr * GSTR + qcol];
            uint32_t b1 = Bs[nr * GSTR + qcol + 4];
            mma_tf32(acc[0][nt], afr[0], b0, b1);
            mma_tf32(acc[1][nt], afr[1], b0, b1);
        }
        __syncthreads();
    }

    // epilogue: scale by invn[r]*invn[c], subtract identity, rowmax
    const float* invb = invn + b * NC;
    float ir[2][2];
#pragma unroll
    for (int mi = 0; mi < 2; mi++) {
        int r = r0 + w_row * 32 + mi * 16 + qrow;
        ir[mi][0] = invb[r];
        ir[mi][1] = invb[r + 8];
    }
    float ic[8][2];
#pragma unroll
    for (int nt = 0; nt < 8; nt++) {
        int c = c0 + w_col * 64 + nt * 8 + qcol * 2;
        ic[nt][0] = invb[c];
        ic[nt][1] = invb[c + 1];
    }
    float rmx[2][2] = {{-1e30f, -1e30f}, {-1e30f, -1e30f}};
#pragma unroll
    for (int mi = 0; mi < 2; mi++)
#pragma unroll
        for (int h = 0; h < 2; h++) {
            int r = r0 + w_row * 32 + mi * 16 + qrow + h * 8;
            float m = -1e30f;
#pragma unroll
            for (int nt = 0; nt < 8; nt++) {
#pragma unroll
                for (int j = 0; j < 2; j++) {
                    int c = c0 + w_col * 64 + nt * 8 + qcol * 2 + j;
                    float v = acc[mi][nt][h * 2 + j] * ir[mi][h] * ic[nt][j] - (r == c ? 1.f : 0.f);
                    m = fmaxf(m, v);
                }
            }
            rmx[mi][h] = m;
        }
    // reduce over the 4 lanes of each quad (they cover different cols)
#pragma unroll
    for (int off = 1; off < 4; off <<= 1)
#pragma unroll
        for (int mi = 0; mi < 2; mi++)
#pragma unroll
            for (int h = 0; h < 2; h++)
                rmx[mi][h] = fmaxf(rmx[mi][h], __shfl_xor_sync(0xffffffffu, rmx[mi][h], off));
    if (qcol == 0) {
#pragma unroll
        for (int mi = 0; mi < 2; mi++)
#pragma unroll
            for (int h = 0; h < 2; h++)
                rmax_s[w_col][w_row * 32 + mi * 16 + qrow + h * 8] = rmx[mi][h];
    }
    __syncthreads();
    if (t < 128)
        rm1p[((size_t)b * 2 + blockIdx.x) * NC + r0 + t] = fmaxf(rmax_s[0][t], rmax_s[1][t]);
}

// ---------------------------------------------------------------------------
// softmax over S2, mean over S1, proto = abar @ V. grid (C, 8), 256 thr.
// ---------------------------------------------------------------------------
__global__ void softmax_proto(const float* __restrict__ S, const float* __restrict__ V,
                              float* __restrict__ proto) {
    int c = blockIdx.x;
    int by = blockIdx.y;
    int t = threadIdx.x;
    __shared__ float Vs[8][256];
    __shared__ float ab[16][8];
    __shared__ float abar[8];

    for (int i = t; i < 8 * 256; i += 256)
        Vs[i >> 8][i & 255] = V[(size_t)c * 8 * 256 + i];
    __syncthreads();

    for (int bi = 0; bi < 16; bi++) {
        int b = by * 16 + bi;
        if (t < 16) {
            const float* row = S + (size_t)(b * 16 + t) * 2048 + c * 8;
            float v[8];
            float mx = -1e30f;
#pragma unroll
            for (int j = 0; j < 8; j++) { v[j] = row[j]; mx = fmaxf(mx, v[j]); }
            float s = 0.f;
#pragma unroll
            for (int j = 0; j < 8; j++) { v[j] = expf(v[j] - mx); s += v[j]; }
            float inv = 1.f / (16.f * s);
#pragma unroll
            for (int j = 0; j < 8; j++) ab[t][j] = v[j] * inv;
        }
        __syncthreads();
        if (t < 8) {
            float s = 0.f;
#pragma unroll
            for (int s1 = 0; s1 < 16; s1++) s += ab[s1][t];
            abar[t] = s;
        }
        __syncthreads();
        float acc = 0.f;
#pragma unroll
        for (int j = 0; j < 8; j++) acc += abar[j] * Vs[j][t];
        proto[((size_t)b * 256 + c) * 256 + t] = acc;
        __syncthreads();
    }
}

// ---------------------------------------------------------------------------
// Per-b: center, n_d, logits, CE. grid 128.
// ---------------------------------------------------------------------------
__global__ void logits_center_ce(const float* __restrict__ proto, const float* __restrict__ left,
                                 const int* __restrict__ ids, float* __restrict__ center,
                                 float* __restrict__ nd, float* __restrict__ ce_part) {
    int b = blockIdx.x;
    int t = threadIdx.x;
    __shared__ float red[256];
    __shared__ float lf[256];
    __shared__ float lgs[256];
    const float* pb = proto + (size_t)b * 65536;

    float s = 0.f;
    for (int c = 0; c < 256; c++) s += pb[(size_t)c * 256 + t];
    float ctr = s * (1.f / 256.f);
    center[b * 256 + t] = ctr;

    float lv = left[b * 256 + t];
    lf[t] = lv;

    float v = lv - ctr;
    red[t] = v * v;
    __syncthreads();
    for (int off = 128; off > 0; off >>= 1) {
        if (t < off) red[t] += red[t + off];
        __syncthreads();
    }
    float nrm = sqrtf(red[0]);
    nd[b * 256 + t] = v / fmaxf(nrm, 1e-12f);
    __syncthreads();

    int w = t >> 5, lane = t & 31;
    float4 l0 = *(const float4*)&lf[lane * 8];
    float4 l1 = *(const float4*)&lf[lane * 8 + 4];
    for (int cc = 0; cc < 32; cc++) {
        int c = w * 32 + cc;
        const float* pr = pb + (size_t)c * 256 + lane * 8;
        float4 x0 = *(const float4*)pr;
        float4 x1 = *(const float4*)(pr + 4);
        float d = x0.x * l0.x + x0.y * l0.y + x0.z * l0.z + x0.w * l0.w
                + x1.x * l1.x + x1.y * l1.y + x1.z * l1.z + x1.w * l1.w;
#pragma unroll
        for (int off = 16; off > 0; off >>= 1) d += __shfl_xor_sync(0xffffffffu, d, off);
        if (lane == 0) lgs[c] = d * (1.0f / 0.9f);
    }
    __syncthreads();

    float lg = lgs[t];
    red[t] = lg;
    __syncthreads();
    for (int off = 128; off > 0; off >>= 1) {
        if (t < off) red[t] = fmaxf(red[t], red[t + off]);
        __syncthreads();
    }
    float mx = red[0];
    __syncthreads();
    red[t] = expf(lg - mx);
    __syncthreads();
    for (int off = 128; off > 0; off >>= 1) {
        if (t < off) red[t] += red[t + off];
        __syncthreads();
    }
    if (t == 0) {
        float lse = mx + logf(red[0]);
        ce_part[b] = lse - lgs[ids[b]];
    }
}

// ---------------------------------------------------------------------------
// invn: 1/max(||proto - center||, eps). warp per row, grid 4096.
// ---------------------------------------------------------------------------
__global__ void center_invnorm(const float* __restrict__ proto, const float* __restrict__ center,
                               float* __restrict__ invn) {
    int t = threadIdx.x;
    int w = t >> 5, lane = t & 31;
    int i = blockIdx.x * 8 + w;
    int b = i >> 8;
    const float* pr = proto + (size_t)i * 256 + lane * 8;
    const float* cr = center + b * 256 + lane * 8;
    float4 x0 = *(const float4*)pr;
    float4 x1 = *(const float4*)(pr + 4);
    float4 c0 = *(const float4*)cr;
    float4 c1 = *(const float4*)(cr + 4);
    float dx;
    float s = 0.f;
    dx = x0.x - c0.x; s += dx * dx;
    dx = x0.y - c0.y; s += dx * dx;
    dx = x0.z - c0.z; s += dx * dx;
    dx = x0.w - c0.w; s += dx * dx;
    dx = x1.x - c1.x; s += dx * dx;
    dx = x1.y - c1.y; s += dx * dx;
    dx = x1.z - c1.z; s += dx * dx;
    dx = x1.w - c1.w; s += dx * dx;
#pragma unroll
    for (int off = 16; off > 0; off >>= 1) s += __shfl_xor_sync(0xffffffffu, s, off);
    if (lane == 0) invn[i] = 1.f / fmaxf(sqrtf(s), 1e-12f);
}

// ---------------------------------------------------------------------------
// loss2: dcos rowmax.
// ---------------------------------------------------------------------------
__global__ void dcos_rowmax(const float* __restrict__ nd, float* __restrict__ rowmax2) {
    int i = blockIdx.x;
    int t = threadIdx.x;
    __shared__ float xi[256];
    __shared__ float red[256];
    xi[t] = nd[i * 256 + t];
    __syncthreads();
    float m = -1e30f;
    if (t < 128) {
        float s = 0.f;
        const float* xj = nd + t * 256;
        for (int d = 0; d < 256; d++) s += xi[d] * xj[d];
        m = s - (i == t ? 1.f : 0.f);
    }
    red[t] = m;
    __syncthreads();
    for (int off = 128; off > 0; off >>= 1) {
        if (t < off) red[t] = fmaxf(red[t], red[t + off]);
        __syncthreads();
    }
    if (t == 0) rowmax2[i] = red[0];
}

// ---------------------------------------------------------------------------
// Final deterministic reduction.
// ---------------------------------------------------------------------------
__global__ void finalize(const float* __restrict__ ce_part, const float* __restrict__ rm1p,
                         const float* __restrict__ rm2, float* __restrict__ out, int out_size) {
    int t = threadIdx.x;
    __shared__ float ra[256], rb[256], rc[256];
    float a = 0.f, b2 = 0.f, c2 = 0.f;
    for (int i = t; i < 128; i += 256) { a += ce_part[i]; c2 += rm2[i]; }
    for (int i = t; i < 32768; i += 256) {
        int b = i >> 8, r = i & 255;
        float v = fmaxf(rm1p[((size_t)b * 2 + 0) * 256 + r], rm1p[((size_t)b * 2 + 1) * 256 + r]);
        b2 += v;
    }
    ra[t] = a; rb[t] = b2; rc[t] = c2;
    __syncthreads();
    for (int off = 128; off > 0; off >>= 1) {
        if (t < off) {
            ra[t] += ra[t + off];
            rb[t] += rb[t + off];
            rc[t] += rc[t + off];
        }
        __syncthreads();
    }
    if (t == 0) {
        float loss = ra[0] / 128.f + 0.7f * (rb[0] / 32768.f + rc[0] / 128.f);
        for (int i = 0; i < out_size; i++) out[i] = loss;
    }
}

// ---------------------------------------------------------------------------
extern "C" void kernel_launch(void* const* d_in, const int* in_sizes, int n_in,
                              void* d_out, int out_size) {
    const float* left = (const float*)d_in[0];
    const float* drug = (const float*)d_in[1];
    const float* sem  = (const float*)d_in[2];
    const float* Wq   = (const float*)d_in[3];
    const float* Wk   = (const float*)d_in[4];
    const float* Wv   = (const float*)d_in[5];
    const int*   ids  = (const int*)d_in[6];
    float* out = (float*)d_out;

    void* p = nullptr;
    cudaGetSymbolAddress(&p, g_scratch);
    Scratch* s = (Scratch*)p;

    const float inv_sqrt_dk = 0.05773502691896258f;  // 1/sqrt(300)

    sgemm64_nn<<<dim3(ND / 64, MQ / 64), 256>>>(drug, Wq, s->Q, MQ, ND, NDQ);
    sgemm64_nn<<<dim3(ND / 64, MK / 64), 256>>>(sem, Wk, s->K, MK, ND, ND);
    sgemm64_nn<<<dim3(ND / 64, MK / 64), 256>>>(sem, Wv, s->V, MK, ND, ND);
    sgemm_tt<<<dim3(MK / BN, MQ / BM), 256>>>(s->Q, s->K, s->S, MQ, MK, ND, inv_sqrt_dk);
    softmax_proto<<<dim3(NC, 8), 256>>>(s->S, s->V, s->proto);
    logits_center_ce<<<NB, 256>>>(s->proto, left, ids, s->center, s->nd, s->ce);
    center_invnorm<<<NB * NC / 8, 256>>>(s->proto, s->center, s->invn);
    gram_rowmax_tf32<<<dim3(2, 2, NB), 256>>>(s->proto, s->center, s->invn, s->rm1p);
    dcos_rowmax<<<NB, 256>>>(s->nd, s->rm2);
    finalize<<<1, 256>>>(s->ce, s->rm1p, s->rm2, out, out_size);
}

// round 4
// speedup vs baseline: 2.1557x; 1.0995x over previous
#include <cuda_runtime.h>
#include <math.h>
#include <stdint.h>

#define NB   128
#define NS1  16
#define NDQ  300
#define NC   256
#define NS2  8
#define ND   256
#define MQ   (NB*NS1) // 2048
#define MK   (NC*NS2) // 2048

struct alignas(128) Scratch {
    float Q[MQ * ND];
    float K[MK * ND];
    float V[MK * ND];
    float S[(size_t)MQ * MK];           // 2048x2048
    float abar[(size_t)NB * NC * NS2];  // 128x256x8
    float proto[(size_t)NB * NC * ND];  // 128x256x256
    float center[NB * ND];
    float nd[NB * ND];
    float invn[NB * NC];
    float ce[NB];
    float rm1p[NB * 2 * NC];
    float rm2[NB];
};
__device__ Scratch g_scratch;

// ---------------------------------------------------------------------------
// tf32 helpers
// ---------------------------------------------------------------------------
__device__ __forceinline__ uint32_t f2tf32(float x) {
    uint32_t r;
    asm("cvt.rna.tf32.f32 %0, %1;" : "=r"(r) : "f"(x));
    return r;
}
__device__ __forceinline__ void mma_tf32(float* d, const uint32_t* a, uint32_t b0, uint32_t b1) {
    asm volatile(
        "mma.sync.aligned.m16n8k8.row.col.f32.tf32.tf32.f32 "
        "{%0,%1,%2,%3},{%4,%5,%6,%7},{%8,%9},{%0,%1,%2,%3};"
        : "+f"(d[0]), "+f"(d[1]), "+f"(d[2]), "+f"(d[3])
        : "r"(a[0]), "r"(a[1]), "r"(a[2]), "r"(a[3]), "r"(b0), "r"(b1));
}

#define GSTR 12

// ---------------------------------------------------------------------------
// 64x64 SGEMM NN (projections; K guard for 300)
// ---------------------------------------------------------------------------
__global__ void sgemm64_nn(const float* __restrict__ A, const float* __restrict__ B,
                           float* __restrict__ C, int M, int N, int K) {
    __shared__ float As[64][17];
    __shared__ float Bs[64][17];
    int tid = threadIdx.x;
    int tx = tid & 15, ty = tid >> 4;
    int m0 = blockIdx.y * 64, n0 = blockIdx.x * 64;
    float acc[4][4];
#pragma unroll
    for (int i = 0; i < 4; i++)
#pragma unroll
        for (int j = 0; j < 4; j++) acc[i][j] = 0.f;
    for (int k0 = 0; k0 < K; k0 += 16) {
#pragma unroll
        for (int i = 0; i < 4; i++) {
            int idx = tid + 256 * i;
            int r = idx >> 4, kk = idx & 15;
            int kg = k0 + kk;
            As[r][kk] = (kg < K) ? A[(size_t)(m0 + r) * K + kg] : 0.f;
        }
#pragma unroll
        for (int i = 0; i < 4; i++) {
            int idx = tid + 256 * i;
            int kk = idx >> 6, n = idx & 63;
            int kg = k0 + kk;
            Bs[n][kk] = (kg < K) ? B[(size_t)kg * N + n0 + n] : 0.f;
        }
        __syncthreads();
#pragma unroll
        for (int kk = 0; kk < 16; kk++) {
            float a[4], bb[4];
#pragma unroll
            for (int i = 0; i < 4; i++) a[i] = As[ty * 4 + i][kk];
#pragma unroll
            for (int j = 0; j < 4; j++) bb[j] = Bs[tx * 4 + j][kk];
#pragma unroll
            for (int i = 0; i < 4; i++)
#pragma unroll
                for (int j = 0; j < 4; j++) acc[i][j] += a[i] * bb[j];
        }
        __syncthreads();
    }
#pragma unroll
    for (int i = 0; i < 4; i++)
#pragma unroll
        for (int j = 0; j < 4; j++)
            C[(size_t)(m0 + ty * 4 + i) * N + n0 + tx * 4 + j] = acc[i][j];
}

// ---------------------------------------------------------------------------
// Scores: C = alpha * A @ B^T via split-tf32 (3 mma passes, ~fp32 accuracy).
// A [2048,256], B [2048,256], C [2048,2048]. grid (16,16), 256 threads.
// ---------------------------------------------------------------------------
__global__ __launch_bounds__(256) void scores_tf32(const float* __restrict__ A,
                                                   const float* __restrict__ B,
                                                   float* __restrict__ C, float alpha) {
    __shared__ uint32_t Ah[128 * GSTR], Al[128 * GSTR];
    __shared__ uint32_t Bh[128 * GSTR], Bl[128 * GSTR];

    int m0 = blockIdx.y * 128, n0 = blockIdx.x * 128;
    int t = threadIdx.x;
    int w = t >> 5, lane = t & 31;
    int w_row = w >> 1, w_col = w & 1;
    int qrow = lane >> 2, qcol = lane & 3;
    int lrow = t >> 1, lpart = (t & 1) * 4;

    const float* Ag = A + (size_t)(m0 + lrow) * ND + lpart;
    const float* Bg = B + (size_t)(n0 + lrow) * ND + lpart;

    float acc[2][8][4];
#pragma unroll
    for (int mi = 0; mi < 2; mi++)
#pragma unroll
        for (int nt = 0; nt < 8; nt++)
#pragma unroll
            for (int j = 0; j < 4; j++) acc[mi][nt][j] = 0.f;

    float4 pa = *(const float4*)(Ag);
    float4 pb = *(const float4*)(Bg);

    for (int k0 = 0; k0 < ND; k0 += 8) {
        float av[4] = {pa.x, pa.y, pa.z, pa.w};
        float bv[4] = {pb.x, pb.y, pb.z, pb.w};
#pragma unroll
        for (int j = 0; j < 4; j++) {
            uint32_t h = f2tf32(av[j]);
            Ah[lrow * GSTR + lpart + j] = h;
            Al[lrow * GSTR + lpart + j] = f2tf32(av[j] - __uint_as_float(h));
            uint32_t hb = f2tf32(bv[j]);
            Bh[lrow * GSTR + lpart + j] = hb;
            Bl[lrow * GSTR + lpart + j] = f2tf32(bv[j] - __uint_as_float(hb));
        }
        __syncthreads();
        if (k0 + 8 < ND) {
            pa = *(const float4*)(Ag + k0 + 8);
            pb = *(const float4*)(Bg + k0 + 8);
        }
        uint32_t afh[2][4], afl[2][4];
#pragma unroll
        for (int mi = 0; mi < 2; mi++) {
            int mr = w_row * 32 + mi * 16 + qrow;
            afh[mi][0] = Ah[mr * GSTR + qcol];
            afh[mi][1] = Ah[(mr + 8) * GSTR + qcol];
            afh[mi][2] = Ah[mr * GSTR + qcol + 4];
            afh[mi][3] = Ah[(mr + 8) * GSTR + qcol + 4];
            afl[mi][0] = Al[mr * GSTR + qcol];
            afl[mi][1] = Al[(mr + 8) * GSTR + qcol];
            afl[mi][2] = Al[mr * GSTR + qcol + 4];
            afl[mi][3] = Al[(mr + 8) * GSTR + qcol + 4];
        }
#pragma unroll
        for (int nt = 0; nt < 8; nt++) {
            int nr = w_col * 64 + nt * 8 + qrow;
            uint32_t bh0 = Bh[nr * GSTR + qcol];
            uint32_t bh1 = Bh[nr * GSTR + qcol + 4];
            uint32_t bl0 = Bl[nr * GSTR + qcol];
            uint32_t bl1 = Bl[nr * GSTR + qcol + 4];
#pragma unroll
            for (int mi = 0; mi < 2; mi++) {
                mma_tf32(acc[mi][nt], afh[mi], bh0, bh1);
                mma_tf32(acc[mi][nt], afh[mi], bl0, bl1);
                mma_tf32(acc[mi][nt], afl[mi], bh0, bh1);
            }
        }
        __syncthreads();
    }
#pragma unroll
    for (int mi = 0; mi < 2; mi++)
#pragma unroll
        for (int h = 0; h < 2; h++) {
            int r = m0 + w_row * 32 + mi * 16 + qrow + h * 8;
#pragma unroll
            for (int nt = 0; nt < 8; nt++) {
                int c = n0 + w_col * 64 + nt * 8 + qcol * 2;
                float2 v = make_float2(alpha * acc[mi][nt][h * 2], alpha * acc[mi][nt][h * 2 + 1]);
                *(float2*)&C[(size_t)r * MK + c] = v;
            }
        }
}

// ---------------------------------------------------------------------------
// abar[b,c,t] = mean_s1 softmax_t(S[b,s1,c,:]). one thread per (b,c).
// grid 128, 256 threads.
// ---------------------------------------------------------------------------
__global__ void abar_kernel(const float* __restrict__ S, float* __restrict__ abar) {
    int b = blockIdx.x;
    int c = threadIdx.x;
    float acc[8];
#pragma unroll
    for (int j = 0; j < 8; j++) acc[j] = 0.f;
    const float* base = S + (size_t)b * 16 * MK + c * 8;
#pragma unroll 4
    for (int s1 = 0; s1 < 16; s1++) {
        const float4* p = (const float4*)(base + (size_t)s1 * MK);
        float4 v0 = p[0], v1 = p[1];
        float v[8] = {v0.x, v0.y, v0.z, v0.w, v1.x, v1.y, v1.z, v1.w};
        float mx = v[0];
#pragma unroll
        for (int j = 1; j < 8; j++) mx = fmaxf(mx, v[j]);
        float s = 0.f;
        float e[8];
#pragma unroll
        for (int j = 0; j < 8; j++) { e[j] = __expf(v[j] - mx); s += e[j]; }
        float inv = 1.f / s;
#pragma unroll
        for (int j = 0; j < 8; j++) acc[j] += e[j] * inv;
    }
    float* o = abar + ((size_t)b * NC + c) * 8;
    float4 o0 = make_float4(acc[0] * 0.0625f, acc[1] * 0.0625f, acc[2] * 0.0625f, acc[3] * 0.0625f);
    float4 o1 = make_float4(acc[4] * 0.0625f, acc[5] * 0.0625f, acc[6] * 0.0625f, acc[7] * 0.0625f);
    *(float4*)o = o0;
    *(float4*)(o + 4) = o1;
}

// ---------------------------------------------------------------------------
// proto[b,c,:] = sum_t abar[b,c,t] * V[c,t,:]. grid (256 c, 4 btile), 256 thr.
// ---------------------------------------------------------------------------
__global__ void proto_kernel(const float* __restrict__ abar, const float* __restrict__ V,
                             float* __restrict__ proto) {
    int c = blockIdx.x;
    int bt = blockIdx.y;
    int t = threadIdx.x;
    __shared__ float Vs[8][256];
    __shared__ float ab[32][8];

    for (int i = t; i < 8 * 256; i += 256)
        Vs[i >> 8][i & 255] = V[(size_t)c * 8 * 256 + i];
    {
        int bl = t >> 3, j = t & 7;
        ab[bl][j] = abar[((size_t)(bt * 32 + bl) * NC + c) * 8 + j];
    }
    __syncthreads();

#pragma unroll 4
    for (int bl = 0; bl < 32; bl++) {
        float a0 = ab[bl][0], a1 = ab[bl][1], a2 = ab[bl][2], a3 = ab[bl][3];
        float a4 = ab[bl][4], a5 = ab[bl][5], a6 = ab[bl][6], a7 = ab[bl][7];
        float acc = a0 * Vs[0][t] + a1 * Vs[1][t] + a2 * Vs[2][t] + a3 * Vs[3][t]
                  + a4 * Vs[4][t] + a5 * Vs[5][t] + a6 * Vs[6][t] + a7 * Vs[7][t];
        proto[((size_t)(bt * 32 + bl) * NC + c) * ND + t] = acc;
    }
}

// ---------------------------------------------------------------------------
// tf32 fused Gram + rowmax (validated round 3).
// ---------------------------------------------------------------------------
__global__ void gram_rowmax_tf32(const float* __restrict__ proto, const float* __restrict__ center,
                                 const float* __restrict__ invn, float* __restrict__ rm1p) {
    __shared__ uint32_t As[128 * GSTR];
    __shared__ uint32_t Bs[128 * GSTR];
    __shared__ float rmax_s[2][128];

    int b = blockIdx.z;
    int r0 = blockIdx.y * 128, c0 = blockIdx.x * 128;
    const float* X = proto + (size_t)b * NC * ND;
    const float* ctr = center + b * ND;

    int t = threadIdx.x;
    int w = t >> 5, lane = t & 31;
    int w_row = w >> 1, w_col = w & 1;
    int qrow = lane >> 2, qcol = lane & 3;
    int lrow = t >> 1;
    int lpart = (t & 1) * 4;

    const float* Ag = X + (size_t)(r0 + lrow) * ND + lpart;
    const float* Bg = X + (size_t)(c0 + lrow) * ND + lpart;

    float acc[2][8][4];
#pragma unroll
    for (int mi = 0; mi < 2; mi++)
#pragma unroll
        for (int nt = 0; nt < 8; nt++)
#pragma unroll
            for (int j = 0; j < 4; j++) acc[mi][nt][j] = 0.f;

    float4 pa = *(const float4*)(Ag);
    float4 pb = *(const float4*)(Bg);
    float4 pc = *(const float4*)(ctr + lpart);

    for (int k0 = 0; k0 < ND; k0 += 8) {
        uint32_t* ad = &As[lrow * GSTR + lpart];
        ad[0] = f2tf32(pa.x - pc.x); ad[1] = f2tf32(pa.y - pc.y);
        ad[2] = f2tf32(pa.z - pc.z); ad[3] = f2tf32(pa.w - pc.w);
        uint32_t* bd = &Bs[lrow * GSTR + lpart];
        bd[0] = f2tf32(pb.x - pc.x); bd[1] = f2tf32(pb.y - pc.y);
        bd[2] = f2tf32(pb.z - pc.z); bd[3] = f2tf32(pb.w - pc.w);
        __syncthreads();
        if (k0 + 8 < ND) {
            pa = *(const float4*)(Ag + k0 + 8);
            pb = *(const float4*)(Bg + k0 + 8);
            pc = *(const float4*)(ctr + k0 + 8 + lpart);
        }
        uint32_t afr[2][4];
#pragma unroll
        for (int mi = 0; mi < 2; mi++) {
            int mr = w_row * 32 + mi * 16 + qrow;
            afr[mi][0] = As[mr * GSTR + qcol];
            afr[mi][1] = As[(mr + 8) * GSTR + qcol];
            afr[mi][2] = As[mr * GSTR + qcol + 4];
            afr[mi][3] = As[(mr + 8) * GSTR + qcol + 4];
        }
#pragma unroll
        for (int nt = 0; nt < 8; nt++) {
            int nr = w_col * 64 + nt * 8 + qrow;
            uint32_t b0 = Bs[nr * GSTR + qcol];
            uint32_t b1 = Bs[nr * GSTR + qcol + 4];
            mma_tf32(acc[0][nt], afr[0], b0, b1);
            mma_tf32(acc[1][nt], afr[1], b0, b1);
        }
        __syncthreads();
    }

    const float* invb = invn + b * NC;
    float ir[2][2];
#pragma unroll
    for (int mi = 0; mi < 2; mi++) {
        int r = r0 + w_row * 32 + mi * 16 + qrow;
        ir[mi][0] = invb[r];
        ir[mi][1] = invb[r + 8];
    }
    float ic[8][2];
#pragma unroll
    for (int nt = 0; nt < 8; nt++) {
        int c = c0 + w_col * 64 + nt * 8 + qcol * 2;
        ic[nt][0] = invb[c];
        ic[nt][1] = invb[c + 1];
    }
    float rmx[2][2] = {{-1e30f, -1e30f}, {-1e30f, -1e30f}};
#pragma unroll
    for (int mi = 0; mi < 2; mi++)
#pragma unroll
        for (int h = 0; h < 2; h++) {
            int r = r0 + w_row * 32 + mi * 16 + qrow + h * 8;
            float m = -1e30f;
#pragma unroll
            for (int nt = 0; nt < 8; nt++) {
#pragma unroll
                for (int j = 0; j < 2; j++) {
                    int c = c0 + w_col * 64 + nt * 8 + qcol * 2 + j;
                    float v = acc[mi][nt][h * 2 + j] * ir[mi][h] * ic[nt][j] - (r == c ? 1.f : 0.f);
                    m = fmaxf(m, v);
                }
            }
            rmx[mi][h] = m;
        }
#pragma unroll
    for (int off = 1; off < 4; off <<= 1)
#pragma unroll
        for (int mi = 0; mi < 2; mi++)
#pragma unroll
            for (int h = 0; h < 2; h++)
                rmx[mi][h] = fmaxf(rmx[mi][h], __shfl_xor_sync(0xffffffffu, rmx[mi][h], off));
    if (qcol == 0) {
#pragma unroll
        for (int mi = 0; mi < 2; mi++)
#pragma unroll
            for (int h = 0; h < 2; h++)
                rmax_s[w_col][w_row * 32 + mi * 16 + qrow + h * 8] = rmx[mi][h];
    }
    __syncthreads();
    if (t < 128)
        rm1p[((size_t)b * 2 + blockIdx.x) * NC + r0 + t] = fmaxf(rmax_s[0][t], rmax_s[1][t]);
}

// ---------------------------------------------------------------------------
// Per-b: center, n_d, logits, CE. grid 128.
// ---------------------------------------------------------------------------
__global__ void logits_center_ce(const float* __restrict__ proto, const float* __restrict__ left,
                                 const int* __restrict__ ids, float* __restrict__ center,
                                 float* __restrict__ nd, float* __restrict__ ce_part) {
    int b = blockIdx.x;
    int t = threadIdx.x;
    __shared__ float red[256];
    __shared__ float lf[256];
    __shared__ float lgs[256];
    const float* pb = proto + (size_t)b * 65536;

    float s = 0.f;
    for (int c = 0; c < 256; c++) s += pb[(size_t)c * 256 + t];
    float ctr = s * (1.f / 256.f);
    center[b * 256 + t] = ctr;

    float lv = left[b * 256 + t];
    lf[t] = lv;

    float v = lv - ctr;
    red[t] = v * v;
    __syncthreads();
    for (int off = 128; off > 0; off >>= 1) {
        if (t < off) red[t] += red[t + off];
        __syncthreads();
    }
    float nrm = sqrtf(red[0]);
    nd[b * 256 + t] = v / fmaxf(nrm, 1e-12f);
    __syncthreads();

    int w = t >> 5, lane = t & 31;
    float4 l0 = *(const float4*)&lf[lane * 8];
    float4 l1 = *(const float4*)&lf[lane * 8 + 4];
    for (int cc = 0; cc < 32; cc++) {
        int c = w * 32 + cc;
        const float* pr = pb + (size_t)c * 256 + lane * 8;
        float4 x0 = *(const float4*)pr;
        float4 x1 = *(const float4*)(pr + 4);
        float d = x0.x * l0.x + x0.y * l0.y + x0.z * l0.z + x0.w * l0.w
                + x1.x * l1.x + x1.y * l1.y + x1.z * l1.z + x1.w * l1.w;
#pragma unroll
        for (int off = 16; off > 0; off >>= 1) d += __shfl_xor_sync(0xffffffffu, d, off);
        if (lane == 0) lgs[c] = d * (1.0f / 0.9f);
    }
    __syncthreads();

    float lg = lgs[t];
    red[t] = lg;
    __syncthreads();
    for (int off = 128; off > 0; off >>= 1) {
        if (t < off) red[t] = fmaxf(red[t], red[t + off]);
        __syncthreads();
    }
    float mx = red[0];
    __syncthreads();
    red[t] = expf(lg - mx);
    __syncthreads();
    for (int off = 128; off > 0; off >>= 1) {
        if (t < off) red[t] += red[t + off];
        __syncthreads();
    }
    if (t == 0) {
        float lse = mx + logf(red[0]);
        ce_part[b] = lse - lgs[ids[b]];
    }
}

// ---------------------------------------------------------------------------
// invn: warp per (b,c) row, grid 4096.
// ---------------------------------------------------------------------------
__global__ void center_invnorm(const float* __restrict__ proto, const float* __restrict__ center,
                               float* __restrict__ invn) {
    int t = threadIdx.x;
    int w = t >> 5, lane = t & 31;
    int i = blockIdx.x * 8 + w;
    int b = i >> 8;
    const float* pr = proto + (size_t)i * 256 + lane * 8;
    const float* cr = center + b * 256 + lane * 8;
    float4 x0 = *(const float4*)pr;
    float4 x1 = *(const float4*)(pr + 4);
    float4 c0 = *(const float4*)cr;
    float4 c1 = *(const float4*)(cr + 4);
    float dx;
    float s = 0.f;
    dx = x0.x - c0.x; s += dx * dx;
    dx = x0.y - c0.y; s += dx * dx;
    dx = x0.z - c0.z; s += dx * dx;
    dx = x0.w - c0.w; s += dx * dx;
    dx = x1.x - c1.x; s += dx * dx;
    dx = x1.y - c1.y; s += dx * dx;
    dx = x1.z - c1.z; s += dx * dx;
    dx = x1.w - c1.w; s += dx * dx;
#pragma unroll
    for (int off = 16; off > 0; off >>= 1) s += __shfl_xor_sync(0xffffffffu, s, off);
    if (lane == 0) invn[i] = 1.f / fmaxf(sqrtf(s), 1e-12f);
}

// ---------------------------------------------------------------------------
__global__ void dcos_rowmax(const float* __restrict__ nd, float* __restrict__ rowmax2) {
    int i = blockIdx.x;
    int t = threadIdx.x;
    __shared__ float xi[256];
    __shared__ float red[256];
    xi[t] = nd[i * 256 + t];
    __syncthreads();
    float m = -1e30f;
    if (t < 128) {
        float s = 0.f;
        const float* xj = nd + t * 256;
        for (int d = 0; d < 256; d++) s += xi[d] * xj[d];
        m = s - (i == t ? 1.f : 0.f);
    }
    red[t] = m;
    __syncthreads();
    for (int off = 128; off > 0; off >>= 1) {
        if (t < off) red[t] = fmaxf(red[t], red[t + off]);
        __syncthreads();
    }
    if (t == 0) rowmax2[i] = red[0];
}

// ---------------------------------------------------------------------------
__global__ void finalize(const float* __restrict__ ce_part, const float* __restrict__ rm1p,
                         const float* __restrict__ rm2, float* __restrict__ out, int out_size) {
    int t = threadIdx.x;
    __shared__ float ra[256], rb[256], rc[256];
    float a = 0.f, b2 = 0.f, c2 = 0.f;
    for (int i = t; i < 128; i += 256) { a += ce_part[i]; c2 += rm2[i]; }
    for (int i = t; i < 32768; i += 256) {
        int b = i >> 8, r = i & 255;
        float v = fmaxf(rm1p[((size_t)b * 2 + 0) * 256 + r], rm1p[((size_t)b * 2 + 1) * 256 + r]);
        b2 += v;
    }
    ra[t] = a; rb[t] = b2; rc[t] = c2;
    __syncthreads();
    for (int off = 128; off > 0; off >>= 1) {
        if (t < off) {
            ra[t] += ra[t + off];
            rb[t] += rb[t + off];
            rc[t] += rc[t + off];
        }
        __syncthreads();
    }
    if (t == 0) {
        float loss = ra[0] / 128.f + 0.7f * (rb[0] / 32768.f + rc[0] / 128.f);
        for (int i = 0; i < out_size; i++) out[i] = loss;
    }
}

// ---------------------------------------------------------------------------
extern "C" void kernel_launch(void* const* d_in, const int* in_sizes, int n_in,
                              void* d_out, int out_size) {
    const float* left = (const float*)d_in[0];
    const float* drug = (const float*)d_in[1];
    const float* sem  = (const float*)d_in[2];
    const float* Wq   = (const float*)d_in[3];
    const float* Wk   = (const float*)d_in[4];
    const float* Wv   = (const float*)d_in[5];
    const int*   ids  = (const int*)d_in[6];
    float* out = (float*)d_out;

    void* p = nullptr;
    cudaGetSymbolAddress(&p, g_scratch);
    Scratch* s = (Scratch*)p;

    const float inv_sqrt_dk = 0.05773502691896258f;  // 1/sqrt(300)

    sgemm64_nn<<<dim3(ND / 64, MQ / 64), 256>>>(drug, Wq, s->Q, MQ, ND, NDQ);
    sgemm64_nn<<<dim3(ND / 64, MK / 64), 256>>>(sem, Wk, s->K, MK, ND, ND);
    sgemm64_nn<<<dim3(ND / 64, MK / 64), 256>>>(sem, Wv, s->V, MK, ND, ND);
    scores_tf32<<<dim3(MK / 128, MQ / 128), 256>>>(s->Q, s->K, s->S, inv_sqrt_dk);
    abar_kernel<<<NB, 256>>>(s->S, s->abar);
    proto_kernel<<<dim3(NC, 4), 256>>>(s->abar, s->V, s->proto);
    logits_center_ce<<<NB, 256>>>(s->proto, left, ids, s->center, s->nd, s->ce);
    center_invnorm<<<NB * NC / 8, 256>>>(s->proto, s->center, s->invn);
    gram_rowmax_tf32<<<dim3(2, 2, NB), 256>>>(s->proto, s->center, s->invn, s->rm1p);
    dcos_rowmax<<<NB, 256>>>(s->nd, s->rm2);
    finalize<<<1, 256>>>(s->ce, s->rm1p, s->rm2, out, out_size);
}

// round 5
// speedup vs baseline: 2.6040x; 1.2079x over previous
#include <cuda_runtime.h>
#include <math.h>
#include <stdint.h>

#define NB   128
#define NS1  16
#define NDQ  300
#define NC   256
#define NS2  8
#define ND   256
#define MQ   (NB*NS1) // 2048
#define MK   (NC*NS2) // 2048

struct alignas(128) Scratch {
    float Q[MQ * ND];
    float K[MK * ND];
    float V[MK * ND];
    float abar[(size_t)NB * NC * NS2];  // 128x256x8
    float proto[(size_t)NB * NC * ND];  // 128x256x256
    float center[NB * ND];
    float nd[NB * ND];
    float invn[NB * NC];
    float ce[NB];
    float rm1p[NB * 2 * NC];
    float rm2[NB];
};
__device__ Scratch g_scratch;

// ---------------------------------------------------------------------------
// helpers
// ---------------------------------------------------------------------------
__device__ __forceinline__ uint32_t f2tf32(float x) {
    uint32_t r;
    asm("cvt.rna.tf32.f32 %0, %1;" : "=r"(r) : "f"(x));
    return r;
}
__device__ __forceinline__ void mma_tf32(float* d, const uint32_t* a, uint32_t b0, uint32_t b1) {
    asm volatile(
        "mma.sync.aligned.m16n8k8.row.col.f32.tf32.tf32.f32 "
        "{%0,%1,%2,%3},{%4,%5,%6,%7},{%8,%9},{%0,%1,%2,%3};"
        : "+f"(d[0]), "+f"(d[1]), "+f"(d[2]), "+f"(d[3])
        : "r"(a[0]), "r"(a[1]), "r"(a[2]), "r"(a[3]), "r"(b0), "r"(b1));
}

// exp(x) for x <= 0, FMA pipe only (no MUFU). |rel err| ~1e-7.
__device__ __forceinline__ float fexp(float x) {
    x = fmaxf(x, -80.f);
    const float L2E = 1.4426950408889634f;
    float t = fmaf(x, L2E, 12582912.f);   // round-to-nearest int via magic
    float n = t - 12582912.f;
    float f = fmaf(x, L2E, -n);           // f in [-0.5, 0.5]
    float p = 0.0001540353f;
    p = fmaf(p, f, 0.0013333558f);
    p = fmaf(p, f, 0.0096181291f);
    p = fmaf(p, f, 0.0555041087f);
    p = fmaf(p, f, 0.2402265069f);
    p = fmaf(p, f, 0.6931471806f);
    p = fmaf(p, f, 1.0f);
    int ni = (__float_as_int(t) & 0x7FFFFF) - 0x400000;  // = (int)n
    return __int_as_float((ni + 127) << 23) * p;
}

// 1/x for x in [~0.5, 16] via magic + 3 Newton iters, FMA pipe only.
__device__ __forceinline__ float frcp(float x) {
    float r = __uint_as_float(0x7EF311C3u - __float_as_uint(x));
    r = r * (2.f - x * r);
    r = r * (2.f - x * r);
    r = r * (2.f - x * r);
    return r;
}

#define GSTR 12

// ---------------------------------------------------------------------------
// 64x64 SGEMM NN (projections; K guard for 300)
// ---------------------------------------------------------------------------
__global__ void sgemm64_nn(const float* __restrict__ A, const float* __restrict__ B,
                           float* __restrict__ C, int M, int N, int K) {
    __shared__ float As[64][17];
    __shared__ float Bs[64][17];
    int tid = threadIdx.x;
    int tx = tid & 15, ty = tid >> 4;
    int m0 = blockIdx.y * 64, n0 = blockIdx.x * 64;
    float acc[4][4];
#pragma unroll
    for (int i = 0; i < 4; i++)
#pragma unroll
        for (int j = 0; j < 4; j++) acc[i][j] = 0.f;
    for (int k0 = 0; k0 < K; k0 += 16) {
#pragma unroll
        for (int i = 0; i < 4; i++) {
            int idx = tid + 256 * i;
            int r = idx >> 4, kk = idx & 15;
            int kg = k0 + kk;
            As[r][kk] = (kg < K) ? A[(size_t)(m0 + r) * K + kg] : 0.f;
        }
#pragma unroll
        for (int i = 0; i < 4; i++) {
            int idx = tid + 256 * i;
            int kk = idx >> 6, n = idx & 63;
            int kg = k0 + kk;
            Bs[n][kk] = (kg < K) ? B[(size_t)kg * N + n0 + n] : 0.f;
        }
        __syncthreads();
#pragma unroll
        for (int kk = 0; kk < 16; kk++) {
            float a[4], bb[4];
#pragma unroll
            for (int i = 0; i < 4; i++) a[i] = As[ty * 4 + i][kk];
#pragma unroll
            for (int j = 0; j < 4; j++) bb[j] = Bs[tx * 4 + j][kk];
#pragma unroll
            for (int i = 0; i < 4; i++)
#pragma unroll
                for (int j = 0; j < 4; j++) acc[i][j] += a[i] * bb[j];
        }
        __syncthreads();
    }
#pragma unroll
    for (int i = 0; i < 4; i++)
#pragma unroll
        for (int j = 0; j < 4; j++)
            C[(size_t)(m0 + ty * 4 + i) * N + n0 + tx * 4 + j] = acc[i][j];
}

// ---------------------------------------------------------------------------
// FUSED: scores (tf32 single-pass) + softmax over s2 + mean over s1 -> abar.
// A=Q [2048,256], B=K [2048,256]. grid (16,16), 256 threads.
// Block tile 128x128 = 8 drugs x 16 classes, fully self-contained.
// ---------------------------------------------------------------------------
__global__ __launch_bounds__(256) void scores_abar_tf32(const float* __restrict__ A,
                                                        const float* __restrict__ B,
                                                        float* __restrict__ abar, float alpha) {
    __shared__ uint32_t Ah[128 * GSTR];
    __shared__ uint32_t Bh[128 * GSTR];

    int m0 = blockIdx.y * 128, n0 = blockIdx.x * 128;
    int t = threadIdx.x;
    int w = t >> 5, lane = t & 31;
    int w_row = w >> 1, w_col = w & 1;
    int qrow = lane >> 2, qcol = lane & 3;
    int lrow = t >> 1, lpart = (t & 1) * 4;

    const float* Ag = A + (size_t)(m0 + lrow) * ND + lpart;
    const float* Bg = B + (size_t)(n0 + lrow) * ND + lpart;

    float acc[2][8][4];
#pragma unroll
    for (int mi = 0; mi < 2; mi++)
#pragma unroll
        for (int nt = 0; nt < 8; nt++)
#pragma unroll
            for (int j = 0; j < 4; j++) acc[mi][nt][j] = 0.f;

    float4 pa = *(const float4*)(Ag);
    float4 pb = *(const float4*)(Bg);

    for (int k0 = 0; k0 < ND; k0 += 8) {
        uint32_t* ad = &Ah[lrow * GSTR + lpart];
        ad[0] = f2tf32(pa.x); ad[1] = f2tf32(pa.y);
        ad[2] = f2tf32(pa.z); ad[3] = f2tf32(pa.w);
        uint32_t* bd = &Bh[lrow * GSTR + lpart];
        bd[0] = f2tf32(pb.x); bd[1] = f2tf32(pb.y);
        bd[2] = f2tf32(pb.z); bd[3] = f2tf32(pb.w);
        __syncthreads();
        if (k0 + 8 < ND) {
            pa = *(const float4*)(Ag + k0 + 8);
            pb = *(const float4*)(Bg + k0 + 8);
        }
        uint32_t afr[2][4];
#pragma unroll
        for (int mi = 0; mi < 2; mi++) {
            int mr = w_row * 32 + mi * 16 + qrow;
            afr[mi][0] = Ah[mr * GSTR + qcol];
            afr[mi][1] = Ah[(mr + 8) * GSTR + qcol];
            afr[mi][2] = Ah[mr * GSTR + qcol + 4];
            afr[mi][3] = Ah[(mr + 8) * GSTR + qcol + 4];
        }
#pragma unroll
        for (int nt = 0; nt < 8; nt++) {
            int nr = w_col * 64 + nt * 8 + qrow;
            uint32_t b0 = Bh[nr * GSTR + qcol];
            uint32_t b1 = Bh[nr * GSTR + qcol + 4];
            mma_tf32(acc[0][nt], afr[0], b0, b1);
            mma_tf32(acc[1][nt], afr[1], b0, b1);
        }
        __syncthreads();
    }

    // Epilogue: per (mi,nt) one warp holds a full (drug b, class c) block:
    // 16 rows (s1) x 8 cols (s2). softmax over cols, mean over rows.
    const float inv16 = 1.f / 16.f;
#pragma unroll
    for (int mi = 0; mi < 2; mi++) {
        int b = (m0 >> 4) + w_row * 2 + mi;
#pragma unroll
        for (int nt = 0; nt < 8; nt++) {
            int c = (n0 >> 3) + w_col * 8 + nt;
            float v00 = acc[mi][nt][0] * alpha;   // row qrow,   col qcol*2
            float v01 = acc[mi][nt][1] * alpha;   // row qrow,   col qcol*2+1
            float v10 = acc[mi][nt][2] * alpha;   // row qrow+8, col qcol*2
            float v11 = acc[mi][nt][3] * alpha;   // row qrow+8, col qcol*2+1
            // row max over the 8 class cols (quad = 4 lanes x 2 vals)
            float mx0 = fmaxf(v00, v01), mx1 = fmaxf(v10, v11);
            mx0 = fmaxf(mx0, __shfl_xor_sync(0xffffffffu, mx0, 1));
            mx0 = fmaxf(mx0, __shfl_xor_sync(0xffffffffu, mx0, 2));
            mx1 = fmaxf(mx1, __shfl_xor_sync(0xffffffffu, mx1, 1));
            mx1 = fmaxf(mx1, __shfl_xor_sync(0xffffffffu, mx1, 2));
            float e00 = fexp(v00 - mx0), e01 = fexp(v01 - mx0);
            float e10 = fexp(v10 - mx1), e11 = fexp(v11 - mx1);
            float s0 = e00 + e01, s1 = e10 + e11;
            s0 += __shfl_xor_sync(0xffffffffu, s0, 1);
            s0 += __shfl_xor_sync(0xffffffffu, s0, 2);
            s1 += __shfl_xor_sync(0xffffffffu, s1, 1);
            s1 += __shfl_xor_sync(0xffffffffu, s1, 2);
            float r0 = frcp(s0), r1 = frcp(s1);
            float a0 = e00 * r0 + e10 * r1;   // col qcol*2   : sum of 2 rows
            float a1 = e01 * r0 + e11 * r1;   // col qcol*2+1
            // sum over the 8 qrow groups -> all 16 rows
            a0 += __shfl_xor_sync(0xffffffffu, a0, 4);
            a1 += __shfl_xor_sync(0xffffffffu, a1, 4);
            a0 += __shfl_xor_sync(0xffffffffu, a0, 8);
            a1 += __shfl_xor_sync(0xffffffffu, a1, 8);
            a0 += __shfl_xor_sync(0xffffffffu, a0, 16);
            a1 += __shfl_xor_sync(0xffffffffu, a1, 16);
            if (qrow == 0) {
                float2 v = make_float2(a0 * inv16, a1 * inv16);
                *(float2*)&abar[((size_t)b * NC + c) * 8 + qcol * 2] = v;
            }
        }
    }
}

// ---------------------------------------------------------------------------
// proto[b,c,:] = sum_t abar[b,c,t] * V[c,t,:]. grid (256 c, 4 btile), 256 thr.
// ---------------------------------------------------------------------------
__global__ void proto_kernel(const float* __restrict__ abar, const float* __restrict__ V,
                             float* __restrict__ proto) {
    int c = blockIdx.x;
    int bt = blockIdx.y;
    int t = threadIdx.x;
    __shared__ float Vs[8][256];
    __shared__ float ab[32][8];

    for (int i = t; i < 8 * 256; i += 256)
        Vs[i >> 8][i & 255] = V[(size_t)c * 8 * 256 + i];
    {
        int bl = t >> 3, j = t & 7;
        ab[bl][j] = abar[((size_t)(bt * 32 + bl) * NC + c) * 8 + j];
    }
    __syncthreads();

#pragma unroll 4
    for (int bl = 0; bl < 32; bl++) {
        float a0 = ab[bl][0], a1 = ab[bl][1], a2 = ab[bl][2], a3 = ab[bl][3];
        float a4 = ab[bl][4], a5 = ab[bl][5], a6 = ab[bl][6], a7 = ab[bl][7];
        float acc = a0 * Vs[0][t] + a1 * Vs[1][t] + a2 * Vs[2][t] + a3 * Vs[3][t]
                  + a4 * Vs[4][t] + a5 * Vs[5][t] + a6 * Vs[6][t] + a7 * Vs[7][t];
        proto[((size_t)(bt * 32 + bl) * NC + c) * ND + t] = acc;
    }
}

// ---------------------------------------------------------------------------
// tf32 fused Gram + rowmax (validated).
// ---------------------------------------------------------------------------
__global__ void gram_rowmax_tf32(const float* __restrict__ proto, const float* __restrict__ center,
                                 const float* __restrict__ invn, float* __restrict__ rm1p) {
    __shared__ uint32_t As[128 * GSTR];
    __shared__ uint32_t Bs[128 * GSTR];
    __shared__ float rmax_s[2][128];

    int b = blockIdx.z;
    int r0 = blockIdx.y * 128, c0 = blockIdx.x * 128;
    const float* X = proto + (size_t)b * NC * ND;
    const float* ctr = center + b * ND;

    int t = threadIdx.x;
    int w = t >> 5, lane = t & 31;
    int w_row = w >> 1, w_col = w & 1;
    int qrow = lane >> 2, qcol = lane & 3;
    int lrow = t >> 1;
    int lpart = (t & 1) * 4;

    const float* Ag = X + (size_t)(r0 + lrow) * ND + lpart;
    const float* Bg = X + (size_t)(c0 + lrow) * ND + lpart;

    float acc[2][8][4];
#pragma unroll
    for (int mi = 0; mi < 2; mi++)
#pragma unroll
        for (int nt = 0; nt < 8; nt++)
#pragma unroll
            for (int j = 0; j < 4; j++) acc[mi][nt][j] = 0.f;

    float4 pa = *(const float4*)(Ag);
    float4 pb = *(const float4*)(Bg);
    float4 pc = *(const float4*)(ctr + lpart);

    for (int k0 = 0; k0 < ND; k0 += 8) {
        uint32_t* ad = &As[lrow * GSTR + lpart];
        ad[0] = f2tf32(pa.x - pc.x); ad[1] = f2tf32(pa.y - pc.y);
        ad[2] = f2tf32(pa.z - pc.z); ad[3] = f2tf32(pa.w - pc.w);
        uint32_t* bd = &Bs[lrow * GSTR + lpart];
        bd[0] = f2tf32(pb.x - pc.x); bd[1] = f2tf32(pb.y - pc.y);
        bd[2] = f2tf32(pb.z - pc.z); bd[3] = f2tf32(pb.w - pc.w);
        __syncthreads();
        if (k0 + 8 < ND) {
            pa = *(const float4*)(Ag + k0 + 8);
            pb = *(const float4*)(Bg + k0 + 8);
            pc = *(const float4*)(ctr + k0 + 8 + lpart);
        }
        uint32_t afr[2][4];
#pragma unroll
        for (int mi = 0; mi < 2; mi++) {
            int mr = w_row * 32 + mi * 16 + qrow;
            afr[mi][0] = As[mr * GSTR + qcol];
            afr[mi][1] = As[(mr + 8) * GSTR + qcol];
            afr[mi][2] = As[mr * GSTR + qcol + 4];
            afr[mi][3] = As[(mr + 8) * GSTR + qcol + 4];
        }
#pragma unroll
        for (int nt = 0; nt < 8; nt++) {
            int nr = w_col * 64 + nt * 8 + qrow;
            uint32_t b0 = Bs[nr * GSTR + qcol];
            uint32_t b1 = Bs[nr * GSTR + qcol + 4];
            mma_tf32(acc[0][nt], afr[0], b0, b1);
            mma_tf32(acc[1][nt], afr[1], b0, b1);
        }
        __syncthreads();
    }

    const float* invb = invn + b * NC;
    float ir[2][2];
#pragma unroll
    for (int mi = 0; mi < 2; mi++) {
        int r = r0 + w_row * 32 + mi * 16 + qrow;
        ir[mi][0] = invb[r];
        ir[mi][1] = invb[r + 8];
    }
    float ic[8][2];
#pragma unroll
    for (int nt = 0; nt < 8; nt++) {
        int c = c0 + w_col * 64 + nt * 8 + qcol * 2;
        ic[nt][0] = invb[c];
        ic[nt][1] = invb[c + 1];
    }
    float rmx[2][2] = {{-1e30f, -1e30f}, {-1e30f, -1e30f}};
#pragma unroll
    for (int mi = 0; mi < 2; mi++)
#pragma unroll
        for (int h = 0; h < 2; h++) {
            int r = r0 + w_row * 32 + mi * 16 + qrow + h * 8;
            float m = -1e30f;
#pragma unroll
            for (int nt = 0; nt < 8; nt++) {
#pragma unroll
                for (int j = 0; j < 2; j++) {
                    int c = c0 + w_col * 64 + nt * 8 + qcol * 2 + j;
                    float v = acc[mi][nt][h * 2 + j] * ir[mi][h] * ic[nt][j] - (r == c ? 1.f : 0.f);
                    m = fmaxf(m, v);
                }
            }
            rmx[mi][h] = m;
        }
#pragma unroll
    for (int off = 1; off < 4; off <<= 1)
#pragma unroll
        for (int mi = 0; mi < 2; mi++)
#pragma unroll
            for (int h = 0; h < 2; h++)
                rmx[mi][h] = fmaxf(rmx[mi][h], __shfl_xor_sync(0xffffffffu, rmx[mi][h], off));
    if (qcol == 0) {
#pragma unroll
        for (int mi = 0; mi < 2; mi++)
#pragma unroll
            for (int h = 0; h < 2; h++)
                rmax_s[w_col][w_row * 32 + mi * 16 + qrow + h * 8] = rmx[mi][h];
    }
    __syncthreads();
    if (t < 128)
        rm1p[((size_t)b * 2 + blockIdx.x) * NC + r0 + t] = fmaxf(rmax_s[0][t], rmax_s[1][t]);
}

// ---------------------------------------------------------------------------
// Per-b: center, n_d, logits, CE. grid 128.
// ---------------------------------------------------------------------------
__global__ void logits_center_ce(const float* __restrict__ proto, const float* __restrict__ left,
                                 const int* __restrict__ ids, float* __restrict__ center,
                                 float* __restrict__ nd, float* __restrict__ ce_part) {
    int b = blockIdx.x;
    int t = threadIdx.x;
    __shared__ float red[256];
    __shared__ float lf[256];
    __shared__ float lgs[256];
    const float* pb = proto + (size_t)b * 65536;

    float s = 0.f;
    for (int c = 0; c < 256; c++) s += pb[(size_t)c * 256 + t];
    float ctr = s * (1.f / 256.f);
    center[b * 256 + t] = ctr;

    float lv = left[b * 256 + t];
    lf[t] = lv;

    float v = lv - ctr;
    red[t] = v * v;
    __syncthreads();
    for (int off = 128; off > 0; off >>= 1) {
        if (t < off) red[t] += red[t + off];
        __syncthreads();
    }
    float nrm = sqrtf(red[0]);
    nd[b * 256 + t] = v / fmaxf(nrm, 1e-12f);
    __syncthreads();

    int w = t >> 5, lane = t & 31;
    float4 l0 = *(const float4*)&lf[lane * 8];
    float4 l1 = *(const float4*)&lf[lane * 8 + 4];
    for (int cc = 0; cc < 32; cc++) {
        int c = w * 32 + cc;
        const float* pr = pb + (size_t)c * 256 + lane * 8;
        float4 x0 = *(const float4*)pr;
        float4 x1 = *(const float4*)(pr + 4);
        float d = x0.x * l0.x + x0.y * l0.y + x0.z * l0.z + x0.w * l0.w
                + x1.x * l1.x + x1.y * l1.y + x1.z * l1.z + x1.w * l1.w;
#pragma unroll
        for (int off = 16; off > 0; off >>= 1) d += __shfl_xor_sync(0xffffffffu, d, off);
        if (lane == 0) lgs[c] = d * (1.0f / 0.9f);
    }
    __syncthreads();

    float lg = lgs[t];
    red[t] = lg;
    __syncthreads();
    for (int off = 128; off > 0; off >>= 1) {
        if (t < off) red[t] = fmaxf(red[t], red[t + off]);
        __syncthreads();
    }
    float mx = red[0];
    __syncthreads();
    red[t] = expf(lg - mx);
    __syncthreads();
    for (int off = 128; off > 0; off >>= 1) {
        if (t < off) red[t] += red[t + off];
        __syncthreads();
    }
    if (t == 0) {
        float lse = mx + logf(red[0]);
        ce_part[b] = lse - lgs[ids[b]];
    }
}

// ---------------------------------------------------------------------------
// invn: warp per (b,c) row, grid 4096.
// ---------------------------------------------------------------------------
__global__ void center_invnorm(const float* __restrict__ proto, const float* __restrict__ center,
                               float* __restrict__ invn) {
    int t = threadIdx.x;
    int w = t >> 5, lane = t & 31;
    int i = blockIdx.x * 8 + w;
    int b = i >> 8;
    const float* pr = proto + (size_t)i * 256 + lane * 8;
    const float* cr = center + b * 256 + lane * 8;
    float4 x0 = *(const float4*)pr;
    float4 x1 = *(const float4*)(pr + 4);
    float4 c0 = *(const float4*)cr;
    float4 c1 = *(const float4*)(cr + 4);
    float dx;
    float s = 0.f;
    dx = x0.x - c0.x; s += dx * dx;
    dx = x0.y - c0.y; s += dx * dx;
    dx = x0.z - c0.z; s += dx * dx;
    dx = x0.w - c0.w; s += dx * dx;
    dx = x1.x - c1.x; s += dx * dx;
    dx = x1.y - c1.y; s += dx * dx;
    dx = x1.z - c1.z; s += dx * dx;
    dx = x1.w - c1.w; s += dx * dx;
#pragma unroll
    for (int off = 16; off > 0; off >>= 1) s += __shfl_xor_sync(0xffffffffu, s, off);
    if (lane == 0) invn[i] = 1.f / fmaxf(sqrtf(s), 1e-12f);
}

// ---------------------------------------------------------------------------
__global__ void dcos_rowmax(const float* __restrict__ nd, float* __restrict__ rowmax2) {
    int i = blockIdx.x;
    int t = threadIdx.x;
    __shared__ float xi[256];
    __shared__ float red[256];
    xi[t] = nd[i * 256 + t];
    __syncthreads();
    float m = -1e30f;
    if (t < 128) {
        float s = 0.f;
        const float* xj = nd + t * 256;
        for (int d = 0; d < 256; d++) s += xi[d] * xj[d];
        m = s - (i == t ? 1.f : 0.f);
    }
    red[t] = m;
    __syncthreads();
    for (int off = 128; off > 0; off >>= 1) {
        if (t < off) red[t] = fmaxf(red[t], red[t + off]);
        __syncthreads();
    }
    if (t == 0) rowmax2[i] = red[0];
}

// ---------------------------------------------------------------------------
__global__ void finalize(const float* __restrict__ ce_part, const float* __restrict__ rm1p,
                         const float* __restrict__ rm2, float* __restrict__ out, int out_size) {
    int t = threadIdx.x;
    __shared__ float ra[256], rb[256], rc[256];
    float a = 0.f, b2 = 0.f, c2 = 0.f;
    for (int i = t; i < 128; i += 256) { a += ce_part[i]; c2 += rm2[i]; }
    for (int i = t; i < 32768; i += 256) {
        int b = i >> 8, r = i & 255;
        float v = fmaxf(rm1p[((size_t)b * 2 + 0) * 256 + r], rm1p[((size_t)b * 2 + 1) * 256 + r]);
        b2 += v;
    }
    ra[t] = a; rb[t] = b2; rc[t] = c2;
    __syncthreads();
    for (int off = 128; off > 0; off >>= 1) {
        if (t < off) {
            ra[t] += ra[t + off];
            rb[t] += rb[t + off];
            rc[t] += rc[t + off];
        }
        __syncthreads();
    }
    if (t == 0) {
        float loss = ra[0] / 128.f + 0.7f * (rb[0] / 32768.f + rc[0] / 128.f);
        for (int i = 0; i < out_size; i++) out[i] = loss;
    }
}

// ---------------------------------------------------------------------------
extern "C" void kernel_launch(void* const* d_in, const int* in_sizes, int n_in,
                              void* d_out, int out_size) {
    const float* left = (const float*)d_in[0];
    const float* drug = (const float*)d_in[1];
    const float* sem  = (const float*)d_in[2];
    const float* Wq   = (const float*)d_in[3];
    const float* Wk   = (const float*)d_in[4];
    const float* Wv   = (const float*)d_in[5];
    const int*   ids  = (const int*)d_in[6];
    float* out = (float*)d_out;

    void* p = nullptr;
    cudaGetSymbolAddress(&p, g_scratch);
    Scratch* s = (Scratch*)p;

    const float inv_sqrt_dk = 0.05773502691896258f;  // 1/sqrt(300)

    sgemm64_nn<<<dim3(ND / 64, MQ / 64), 256>>>(drug, Wq, s->Q, MQ, ND, NDQ);
    sgemm64_nn<<<dim3(ND / 64, MK / 64), 256>>>(sem, Wk, s->K, MK, ND, ND);
    sgemm64_nn<<<dim3(ND / 64, MK / 64), 256>>>(sem, Wv, s->V, MK, ND, ND);
    scores_abar_tf32<<<dim3(MK / 128, MQ / 128), 256>>>(s->Q, s->K, s->abar, inv_sqrt_dk);
    proto_kernel<<<dim3(NC, 4), 256>>>(s->abar, s->V, s->proto);
    logits_center_ce<<<NB, 256>>>(s->proto, left, ids, s->center, s->nd, s->ce);
    center_invnorm<<<NB * NC / 8, 256>>>(s->proto, s->center, s->invn);
    gram_rowmax_tf32<<<dim3(2, 2, NB), 256>>>(s->proto, s->center, s->invn, s->rm1p);
    dcos_rowmax<<<NB, 256>>>(s->nd, s->rm2);
    finalize<<<1, 256>>>(s->ce, s->rm1p, s->rm2, out, out_size);
}